// round 2
// baseline (speedup 1.0000x reference)
#include <cuda_runtime.h>
#include <cstdint>
#include <cstddef>

#define CIN 32
#define K1  128
#define K2  512
#define FCD 256
#define MAXN 524288
#define MAXB 16

typedef unsigned long long u64;

// ---------- scratch (device globals; no allocation) ----------
__device__ float g_hT[(size_t)K1 * MAXN];     // h raw, transposed [K1][N]
__device__ float g_att[(size_t)MAXN * K2];    // att raw (pre-BN2) [N][K2]
__device__ float g_w2t[K2 * K1];              // w2 transposed [K1][K2]
__device__ float g_s1[2 * K1];
__device__ float g_bn1[2 * K1];               // a1, c1
__device__ float g_s2[2 * K2];
__device__ float g_bn2[2 * K2];               // a2, c2
__device__ float g_pooled[MAXB * K2 * CIN];   // unscaled att^T x
__device__ float g_resraw[MAXB * FCD];

// ---------- packed f32x2 helpers ----------
__device__ __forceinline__ u64 pk2(float lo, float hi) {
    u64 r; asm("mov.b64 %0, {%1, %2};" : "=l"(r) : "f"(lo), "f"(hi)); return r;
}
__device__ __forceinline__ void fma2(u64 &d, u64 a, u64 b) {
    asm("fma.rn.f32x2 %0, %1, %2, %0;" : "+l"(d) : "l"(a), "l"(b));
}
__device__ __forceinline__ float2 upk2(u64 v) {
    float lo, hi; asm("mov.b64 {%0, %1}, %2;" : "=f"(lo), "=f"(hi) : "l"(v));
    return make_float2(lo, hi);
}

// ---------- zero accumulators + gp region of out ----------
__global__ void k_zero(float* outp, int B) {
    int i = blockIdx.x * blockDim.x + threadIdx.x;
    if (i < B * K2 * CIN) g_pooled[i] = 0.f;
    if (i < 2 * K1) g_s1[i] = 0.f;
    if (i < 2 * K2) g_s2[i] = 0.f;
    if (i < B * K2) outp[B * FCD + i] = 0.f;
}

// ---------- transpose w2 ----------
__global__ void k_prep(const float* __restrict__ w2) {
    int i = blockIdx.x * blockDim.x + threadIdx.x;
    if (i < K2 * K1) { int n = i / K1, k = i % K1; g_w2t[k * K2 + n] = w2[i]; }
}

// ---------- GEMM1: hT[k][p] = x[p]·w1[k] + b1[k] ----------
__global__ __launch_bounds__(256) void k_gemm1(const float* __restrict__ x,
                                               const float* __restrict__ w1,
                                               const float* __restrict__ b1, int N) {
    __shared__ float w1s[K1 * CIN];
    int tid = threadIdx.x;
    for (int i = tid; i < K1 * CIN; i += 256) w1s[i] = w1[i];
    size_t p = (size_t)blockIdx.x * 256 + tid;
    float xr[32];
    const float4* xp = (const float4*)(x + p * CIN);
#pragma unroll
    for (int q = 0; q < 8; q++) {
        float4 v = xp[q];
        xr[4*q] = v.x; xr[4*q+1] = v.y; xr[4*q+2] = v.z; xr[4*q+3] = v.w;
    }
    __syncthreads();
    for (int k = 0; k < K1; k++) {
        float a = b1[k];
        const float4* wr = (const float4*)(w1s + k * CIN);
#pragma unroll
        for (int q = 0; q < 8; q++) {
            float4 wv = wr[q];
            a += xr[4*q]*wv.x + xr[4*q+1]*wv.y + xr[4*q+2]*wv.z + xr[4*q+3]*wv.w;
        }
        g_hT[(size_t)k * N + p] = a;
    }
}

// ---------- BN1 stats over hT rows ----------
__global__ __launch_bounds__(256) void k_stats1(int N) {
    int k = blockIdx.y;
    int per = N >> 5;
    const float* row = g_hT + (size_t)k * N + (size_t)blockIdx.x * per;
    float s = 0.f, q = 0.f;
    for (int i = threadIdx.x * 4; i < per; i += 1024) {
        float4 v = *(const float4*)(row + i);
        s += v.x + v.y + v.z + v.w;
        q += v.x*v.x + v.y*v.y + v.z*v.z + v.w*v.w;
    }
#pragma unroll
    for (int o = 16; o; o >>= 1) {
        s += __shfl_down_sync(0xffffffffu, s, o);
        q += __shfl_down_sync(0xffffffffu, q, o);
    }
    __shared__ float ws[8], wq[8];
    int w = threadIdx.x >> 5;
    if ((threadIdx.x & 31) == 0) { ws[w] = s; wq[w] = q; }
    __syncthreads();
    if (threadIdx.x == 0) {
        float S = 0.f, Q = 0.f;
        for (int i = 0; i < 8; i++) { S += ws[i]; Q += wq[i]; }
        atomicAdd(&g_s1[k], S); atomicAdd(&g_s1[K1 + k], Q);
    }
}

__global__ void k_fin1(const float* __restrict__ g1, const float* __restrict__ be1, float invN) {
    int k = threadIdx.x;
    float mu  = g_s1[k] * invN;
    float var = g_s1[K1 + k] * invN - mu * mu;
    float a = g1[k] * rsqrtf(var + 1e-5f);
    g_bn1[k] = a;
    g_bn1[K1 + k] = fmaf(-mu, a, be1[k]);
}

// ---------- GEMM2: att[p][n] = relu(bn1(h))·w2[n] + b2[n]  (f32x2) ----------
__global__ __launch_bounds__(256) void k_gemm2(const float* __restrict__ b2, int N) {
    __shared__ float As[32][128];
    __shared__ float Bs[32][128];
    int tid = threadIdx.x;
    int ty = tid >> 4, tx = tid & 15;
    size_t p0 = (size_t)blockIdx.x * 128;
    int n0 = blockIdx.y * 128;
    u64 acc[8][4];
#pragma unroll
    for (int i = 0; i < 8; i++)
#pragma unroll
        for (int j = 0; j < 4; j++) acc[i][j] = 0ull;

    for (int kc = 0; kc < K1; kc += 32) {
        __syncthreads();
        for (int i = tid; i < 32 * 128; i += 256) {
            int kk = i >> 7, m = i & 127;
            int kg = kc + kk;
            float v = g_hT[(size_t)kg * N + p0 + m];
            As[kk][m] = fmaxf(fmaf(g_bn1[kg], v, g_bn1[K1 + kg]), 0.f);
        }
        for (int i = tid; i < 32 * 128; i += 256) {
            int kk = i >> 7, n = i & 127;
            Bs[kk][n] = g_w2t[(size_t)(kc + kk) * K2 + n0 + n];
        }
        __syncthreads();
#pragma unroll 4
        for (int kk = 0; kk < 32; kk++) {
            u64 bp[4];
#pragma unroll
            for (int j = 0; j < 4; j++)
                bp[j] = *(const u64*)&Bs[kk][2 * tx + 32 * j];
#pragma unroll
            for (int i = 0; i < 8; i++) {
                float a = As[kk][ty * 8 + i];
                u64 ap = pk2(a, a);
#pragma unroll
                for (int j = 0; j < 4; j++) fma2(acc[i][j], ap, bp[j]);
            }
        }
    }
    const float* b2p = b2 + n0;
#pragma unroll
    for (int i = 0; i < 8; i++) {
        float* orow = g_att + (p0 + ty * 8 + i) * K2 + n0;
#pragma unroll
        for (int j = 0; j < 4; j++) {
            int c = 2 * tx + 32 * j;
            float2 f = upk2(acc[i][j]);
            float2 o; o.x = f.x + b2p[c]; o.y = f.y + b2p[c + 1];
            *(float2*)(orow + c) = o;
        }
    }
}

// ---------- BN2 stats over att columns ----------
__global__ __launch_bounds__(256) void k_stats2(int N) {
    size_t r0 = (size_t)blockIdx.x * 512;
    int c = threadIdx.x * 2;
    float sx = 0.f, sy = 0.f, qx = 0.f, qy = 0.f;
#pragma unroll 4
    for (int r = 0; r < 512; r++) {
        float2 v = *(const float2*)&g_att[(r0 + r) * K2 + c];
        sx += v.x; sy += v.y; qx += v.x * v.x; qy += v.y * v.y;
    }
    atomicAdd(&g_s2[c], sx);      atomicAdd(&g_s2[c + 1], sy);
    atomicAdd(&g_s2[K2 + c], qx); atomicAdd(&g_s2[K2 + c + 1], qy);
}

__global__ void k_fin2(const float* __restrict__ g2, const float* __restrict__ be2, float invN) {
    int k = threadIdx.x;
    float mu  = g_s2[k] * invN;
    float var = g_s2[K2 + k] * invN - mu * mu;
    float a = g2[k] * rsqrtf(var + 1e-5f);
    g_bn2[k] = a;
    g_bn2[K2 + k] = fmaf(-mu, a, be2[k]);
}

// ---------- pooling: pooled[b,k,c] += attn*x ; gp[b,k] += attn ----------
__global__ __launch_bounds__(256) void k_pool(const float* __restrict__ x,
                                              float* __restrict__ gp_out, int L) {
    __shared__ float Att[32][64];
    __shared__ float Xs[32][32];
    int b = blockIdx.x;
    int k0 = blockIdx.y * 64;
    int lsl = L >> 3;
    size_t pbase = (size_t)b * L + (size_t)blockIdx.z * lsl;
    int tid = threadIdx.x;
    int kq = tid >> 2, tx = tid & 3;
    u64 acc[4] = {0ull, 0ull, 0ull, 0ull};
    float gpl = 0.f;
    for (int lc = 0; lc < lsl; lc += 32) {
        __syncthreads();
        for (int i = tid; i < 32 * 64; i += 256) {
            int r = i >> 6, c = i & 63;
            float v = g_att[(pbase + lc + r) * K2 + k0 + c];
            Att[r][c] = fmaxf(fmaf(g_bn2[k0 + c], v, g_bn2[K2 + k0 + c]), 0.f);
        }
        for (int i = tid; i < 32 * 32; i += 256) {
            int r = i >> 5, c = i & 31;
            Xs[r][c] = x[(pbase + lc + r) * CIN + c];
        }
        __syncthreads();
#pragma unroll 4
        for (int l = 0; l < 32; l++) {
            float a = Att[l][kq];
            if (tx == 0) gpl += a;
            u64 ap = pk2(a, a);
#pragma unroll
            for (int j = 0; j < 4; j++) {
                u64 xp = *(const u64*)&Xs[l][tx * 8 + 2 * j];
                fma2(acc[j], ap, xp);
            }
        }
    }
    float* pd = &g_pooled[((size_t)b * K2 + k0 + kq) * CIN + tx * 8];
#pragma unroll
    for (int j = 0; j < 4; j++) {
        float2 f = upk2(acc[j]);
        atomicAdd(&pd[2 * j], f.x);
        atomicAdd(&pd[2 * j + 1], f.y);
    }
    if (tx == 0) atomicAdd(&gp_out[b * K2 + k0 + kq], gpl);
}

// ---------- FC: resraw[b][j] = pooled[b]·wf[j]/L + bf[j] ----------
__global__ __launch_bounds__(256) void k_fc(const float* __restrict__ wf,
                                            const float* __restrict__ bf,
                                            int B, float invL) {
    int j = blockIdx.x;
    int tid = threadIdx.x;
    const float* wrow = wf + (size_t)j * (K2 * CIN);
    float acc[MAXB];
#pragma unroll
    for (int b = 0; b < MAXB; b++) acc[b] = 0.f;
    for (int i = tid; i < K2 * CIN; i += 256) {
        float w = wrow[i];
#pragma unroll
        for (int b = 0; b < MAXB; b++)
            if (b < B) acc[b] += w * g_pooled[(size_t)b * (K2 * CIN) + i];
    }
    __shared__ float red[8][MAXB];
    int lane = tid & 31, w = tid >> 5;
#pragma unroll
    for (int b = 0; b < MAXB; b++) {
        float v = acc[b];
#pragma unroll
        for (int o = 16; o; o >>= 1) v += __shfl_down_sync(0xffffffffu, v, o);
        if (lane == 0) red[w][b] = v;
    }
    __syncthreads();
    if (tid < B) {
        float s = 0.f;
        for (int i = 0; i < 8; i++) s += red[i][tid];
        g_resraw[tid * FCD + j] = fmaf(s, invL, bf[j]);
    }
}

// ---------- final: BN over B, L2 normalize, lengths ----------
__global__ void k_final(float* __restrict__ outp, const float* __restrict__ gf,
                        const float* __restrict__ bef, int B, int L) {
    int j = threadIdx.x;  // 256 threads
    __shared__ float rows[MAXB];
    if (j < B) rows[j] = 0.f;
    __syncthreads();
    float v[MAXB];
    float s = 0.f, q = 0.f;
    for (int b = 0; b < B; b++) {
        v[b] = g_resraw[b * FCD + j];
        s += v[b]; q += v[b] * v[b];
    }
    float invB = 1.f / (float)B;
    float mu = s * invB;
    float var = q * invB - mu * mu;
    float a = gf[j] * rsqrtf(var + 1e-5f);
    float c = fmaf(-mu, a, bef[j]);
    for (int b = 0; b < B; b++) {
        v[b] = fmaf(a, v[b], c);
        atomicAdd(&rows[b], v[b] * v[b]);
    }
    __syncthreads();
    for (int b = 0; b < B; b++)
        outp[b * FCD + j] = v[b] / fmaxf(sqrtf(rows[b]), 1e-12f);
    if (j < B) outp[B * FCD + B * K2 + j] = (float)L;
}

// ---------- launch ----------
extern "C" void kernel_launch(void* const* d_in, const int* in_sizes, int n_in,
                              void* d_out, int out_size) {
    const float* x   = (const float*)d_in[0];
    const float* w1  = (const float*)d_in[1];
    const float* b1  = (const float*)d_in[2];
    const float* g1  = (const float*)d_in[3];
    const float* be1 = (const float*)d_in[4];
    const float* w2  = (const float*)d_in[5];
    const float* b2  = (const float*)d_in[6];
    const float* g2  = (const float*)d_in[7];
    const float* be2 = (const float*)d_in[8];
    const float* wf  = (const float*)d_in[9];
    const float* bf  = (const float*)d_in[10];
    const float* gf  = (const float*)d_in[11];
    const float* bef = (const float*)d_in[12];
    float* outp = (float*)d_out;

    int N = in_sizes[0] / CIN;
    int B = out_size / (FCD + K2 + 1);
    int L = N / B;
    float invN = 1.f / (float)N;
    float invL = 1.f / (float)L;

    k_zero<<<(B * K2 * CIN + 255) / 256, 256>>>(outp, B);
    k_prep<<<(K2 * K1 + 255) / 256, 256>>>(w2);
    k_gemm1<<<N / 256, 256>>>(x, w1, b1, N);
    k_stats1<<<dim3(32, K1), 256>>>(N);
    k_fin1<<<1, K1>>>(g1, be1, invN);
    k_gemm2<<<dim3(N / 128, K2 / 128), 256>>>(b2, N);
    k_stats2<<<N / 512, 256>>>(N);
    k_fin2<<<1, K2>>>(g2, be2, invN);
    k_pool<<<dim3(B, K2 / 64, 8), 256>>>(x, outp + B * FCD, L);
    k_fc<<<FCD, 256>>>(wf, bf, B, invL);
    k_final<<<1, FCD>>>(outp, gf, bef, B, L);
}

// round 4
// speedup vs baseline: 1.4286x; 1.4286x over previous
#include <cuda_runtime.h>
#include <cuda_bf16.h>
#include <cstdint>
#include <cstddef>

#define CIN 32
#define K1  128
#define K2  512
#define FCD 256
#define MAXN 524288
#define MAXB 16

typedef unsigned long long u64;

// ---------- scratch (device globals; no runtime allocation) ----------
__device__ float g_hT[(size_t)K1 * MAXN];     // h raw, transposed [K1][N]
__device__ float g_att[(size_t)MAXN * K2];    // att raw (pre-BN2) [N][K2], fp32
__device__ float g_w2t[K2 * K1];              // w2 transposed [K1][K2]
__device__ float g_s1[2 * K1];
__device__ float g_bn1[2 * K1];               // a1, c1
__device__ float g_s2[2 * K2];
__device__ float g_bn2[2 * K2];               // a2, c2
__device__ float g_pooled[MAXB * K2 * CIN];
__device__ float g_resraw[MAXB * FCD];

// ---------- packed f32x2 helpers ----------
__device__ __forceinline__ u64 pk2(float lo, float hi) {
    u64 r; asm("mov.b64 %0, {%1, %2};" : "=l"(r) : "f"(lo), "f"(hi)); return r;
}
__device__ __forceinline__ void fma2(u64 &d, u64 a, u64 b) {
    asm("fma.rn.f32x2 %0, %1, %2, %0;" : "+l"(d) : "l"(a), "l"(b));
}
__device__ __forceinline__ float2 upk2(u64 v) {
    float lo, hi; asm("mov.b64 {%0, %1}, %2;" : "=f"(lo), "=f"(hi) : "l"(v));
    return make_float2(lo, hi);
}
__device__ __forceinline__ void cpasync16(uint32_t dst, const void* src) {
    asm volatile("cp.async.cg.shared.global [%0], [%1], 16;" :: "r"(dst), "l"(src));
}

// ---------- zero accumulators + gp region of out ----------
__global__ void k_zero(float* outp, int B) {
    int i = blockIdx.x * blockDim.x + threadIdx.x;
    if (i < B * K2 * CIN) g_pooled[i] = 0.f;
    if (i < 2 * K1) g_s1[i] = 0.f;
    if (i < 2 * K2) g_s2[i] = 0.f;
    if (i < B * K2) outp[B * FCD + i] = 0.f;
}

// ---------- transpose w2 ----------
__global__ void k_prep(const float* __restrict__ w2) {
    int i = blockIdx.x * blockDim.x + threadIdx.x;
    if (i < K2 * K1) { int n = i / K1, k = i % K1; g_w2t[k * K2 + n] = w2[i]; }
}

// ---------- GEMM1 (f32x2): hT[k][p] = x[p]·w1[k] + b1[k] ----------
__global__ __launch_bounds__(256) void k_gemm1(const float* __restrict__ x,
                                               const float* __restrict__ w1,
                                               const float* __restrict__ b1, int N) {
    __shared__ __align__(16) float w1s[K1 * CIN];
    int tid = threadIdx.x;
    for (int i = tid; i < K1 * CIN; i += 256) w1s[i] = w1[i];
    size_t p = (size_t)blockIdx.x * 256 + tid;
    u64 xp2[16];
    const float4* xp = (const float4*)(x + p * CIN);
#pragma unroll
    for (int q = 0; q < 8; q++) {
        float4 v = xp[q];
        xp2[2*q]   = pk2(v.x, v.y);
        xp2[2*q+1] = pk2(v.z, v.w);
    }
    __syncthreads();
#pragma unroll 4
    for (int k = 0; k < K1; k++) {
        const u64* wr = (const u64*)(w1s + k * CIN);
        u64 a = 0ull;
#pragma unroll
        for (int q = 0; q < 16; q++) fma2(a, xp2[q], wr[q]);
        float2 f = upk2(a);
        g_hT[(size_t)k * N + p] = f.x + f.y + b1[k];
    }
}

// ---------- BN1 stats over hT rows ----------
__global__ __launch_bounds__(256) void k_stats1(int N) {
    int k = blockIdx.y;
    int per = N >> 5;
    const float* row = g_hT + (size_t)k * N + (size_t)blockIdx.x * per;
    float s = 0.f, q = 0.f;
    for (int i = threadIdx.x * 4; i < per; i += 1024) {
        float4 v = *(const float4*)(row + i);
        s += v.x + v.y + v.z + v.w;
        q += v.x*v.x + v.y*v.y + v.z*v.z + v.w*v.w;
    }
#pragma unroll
    for (int o = 16; o; o >>= 1) {
        s += __shfl_down_sync(0xffffffffu, s, o);
        q += __shfl_down_sync(0xffffffffu, q, o);
    }
    __shared__ float ws[8], wq[8];
    int w = threadIdx.x >> 5;
    if ((threadIdx.x & 31) == 0) { ws[w] = s; wq[w] = q; }
    __syncthreads();
    if (threadIdx.x == 0) {
        float S = 0.f, Q = 0.f;
        for (int i = 0; i < 8; i++) { S += ws[i]; Q += wq[i]; }
        atomicAdd(&g_s1[k], S); atomicAdd(&g_s1[K1 + k], Q);
    }
}

__global__ void k_fin1(const float* __restrict__ g1, const float* __restrict__ be1, float invN) {
    int k = threadIdx.x;
    float mu  = g_s1[k] * invN;
    float var = g_s1[K1 + k] * invN - mu * mu;
    float a = g1[k] * rsqrtf(var + 1e-5f);
    g_bn1[k] = a;
    g_bn1[K1 + k] = fmaf(-mu, a, be1[k]);
}

// ---------- GEMM2: att = relu(bn1(h))·w2 + b2 (fp32 out), fused BN2 stats ----------
// grid: (K2/128 fast, N/128 slow) so same-p blocks share A tiles in L2.
__global__ __launch_bounds__(256, 2) void k_gemm2(const float* __restrict__ b2, int N) {
    __shared__ __align__(16) float As[32][128];
    __shared__ __align__(16) float Bs[2][32][128];
    int tid = threadIdx.x;
    int tx = tid & 15, ty = tid >> 4;
    int n0 = blockIdx.x * 128;
    size_t p0 = (size_t)blockIdx.y * 128;

    int lk[4], lm[4];
#pragma unroll
    for (int q = 0; q < 4; q++) { int f = tid + 256 * q; lk[q] = f >> 5; lm[q] = (f & 31) * 4; }

    u64 acc[4][8];
#pragma unroll
    for (int mp = 0; mp < 4; mp++)
#pragma unroll
        for (int c = 0; c < 8; c++) acc[mp][c] = 0ull;

    // prologue: stage 0
    {
        uint32_t bs0 = (uint32_t)__cvta_generic_to_shared(&Bs[0][0][0]);
#pragma unroll
        for (int q = 0; q < 4; q++)
            cpasync16(bs0 + (uint32_t)(lk[q] * 128 + lm[q]) * 4,
                      &g_w2t[(size_t)lk[q] * K2 + n0 + lm[q]]);
        asm volatile("cp.async.commit_group;\n" ::: "memory");
        float4 Ar[4];
#pragma unroll
        for (int q = 0; q < 4; q++)
            Ar[q] = *(const float4*)&g_hT[(size_t)lk[q] * N + p0 + lm[q]];
#pragma unroll
        for (int q = 0; q < 4; q++) {
            int kg = lk[q];
            float a1 = g_bn1[kg], c1 = g_bn1[K1 + kg];
            float4 v = Ar[q];
            v.x = fmaxf(fmaf(a1, v.x, c1), 0.f);
            v.y = fmaxf(fmaf(a1, v.y, c1), 0.f);
            v.z = fmaxf(fmaf(a1, v.z, c1), 0.f);
            v.w = fmaxf(fmaf(a1, v.w, c1), 0.f);
            *(float4*)&As[lk[q]][lm[q]] = v;
        }
        asm volatile("cp.async.wait_group 0;\n" ::: "memory");
    }
    __syncthreads();

    float4 Ar[4];
    for (int kc = 0; kc < 4; kc++) {
        int kb = (kc + 1) * 32;
        if (kc < 3) {
            uint32_t bsn = (uint32_t)__cvta_generic_to_shared(&Bs[(kc + 1) & 1][0][0]);
#pragma unroll
            for (int q = 0; q < 4; q++)
                cpasync16(bsn + (uint32_t)(lk[q] * 128 + lm[q]) * 4,
                          &g_w2t[(size_t)(kb + lk[q]) * K2 + n0 + lm[q]]);
            asm volatile("cp.async.commit_group;\n" ::: "memory");
#pragma unroll
            for (int q = 0; q < 4; q++)
                Ar[q] = *(const float4*)&g_hT[(size_t)(kb + lk[q]) * N + p0 + lm[q]];
        }
        const float (*Bc)[128] = Bs[kc & 1];
#pragma unroll 2
        for (int kk = 0; kk < 32; kk++) {
            u64 ap[4];
#pragma unroll
            for (int mp = 0; mp < 4; mp++)
                ap[mp] = *(const u64*)&As[kk][ty * 8 + 2 * mp];
            float4 bv0 = *(const float4*)&Bc[kk][4 * tx];
            float4 bv1 = *(const float4*)&Bc[kk][64 + 4 * tx];
            u64 bp[8];
            bp[0] = pk2(bv0.x, bv0.x); bp[1] = pk2(bv0.y, bv0.y);
            bp[2] = pk2(bv0.z, bv0.z); bp[3] = pk2(bv0.w, bv0.w);
            bp[4] = pk2(bv1.x, bv1.x); bp[5] = pk2(bv1.y, bv1.y);
            bp[6] = pk2(bv1.z, bv1.z); bp[7] = pk2(bv1.w, bv1.w);
#pragma unroll
            for (int mp = 0; mp < 4; mp++)
#pragma unroll
                for (int c = 0; c < 8; c++) fma2(acc[mp][c], ap[mp], bp[c]);
        }
        __syncthreads();
        if (kc < 3) {
#pragma unroll
            for (int q = 0; q < 4; q++) {
                int kg = kb + lk[q];
                float a1 = g_bn1[kg], c1 = g_bn1[K1 + kg];
                float4 v = Ar[q];
                v.x = fmaxf(fmaf(a1, v.x, c1), 0.f);
                v.y = fmaxf(fmaf(a1, v.y, c1), 0.f);
                v.z = fmaxf(fmaf(a1, v.z, c1), 0.f);
                v.w = fmaxf(fmaf(a1, v.w, c1), 0.f);
                *(float4*)&As[lk[q]][lm[q]] = v;
            }
            asm volatile("cp.async.wait_group 0;\n" ::: "memory");
            __syncthreads();
        }
    }

    // epilogue: +b2, fp32 store, accumulate BN2 stats on stored values
    float bb[8];
#pragma unroll
    for (int g = 0; g < 2; g++)
#pragma unroll
        for (int cc = 0; cc < 4; cc++) bb[g * 4 + cc] = b2[n0 + 64 * g + 4 * tx + cc];

    float s[8], qq[8];
#pragma unroll
    for (int c = 0; c < 8; c++) { s[c] = 0.f; qq[c] = 0.f; }

#pragma unroll
    for (int mp = 0; mp < 4; mp++) {
        float rv[2][8];
#pragma unroll
        for (int c = 0; c < 8; c++) {
            float2 f = upk2(acc[mp][c]);
            rv[0][c] = f.x + bb[c];
            rv[1][c] = f.y + bb[c];
            s[c] += rv[0][c] + rv[1][c];
            qq[c] += rv[0][c] * rv[0][c] + rv[1][c] * rv[1][c];
        }
#pragma unroll
        for (int rr = 0; rr < 2; rr++) {
            size_t row = p0 + (size_t)(ty * 8 + 2 * mp + rr);
            float* orow = g_att + row * K2 + n0;
            float4 o0, o1;
            o0.x = rv[rr][0]; o0.y = rv[rr][1]; o0.z = rv[rr][2]; o0.w = rv[rr][3];
            o1.x = rv[rr][4]; o1.y = rv[rr][5]; o1.z = rv[rr][6]; o1.w = rv[rr][7];
            *(float4*)(orow + 4 * tx)      = o0;
            *(float4*)(orow + 64 + 4 * tx) = o1;
        }
    }

    // block-level reduce of stats over ty, then one atomic per (col, stat)
    __syncthreads();
    float* redS = &As[0][0];
    float* redQ = &Bs[0][0][0];
#pragma unroll
    for (int g = 0; g < 2; g++)
#pragma unroll
        for (int cc = 0; cc < 4; cc++) {
            int col = 64 * g + 4 * tx + cc;
            redS[ty * 128 + col] = s[g * 4 + cc];
            redQ[ty * 128 + col] = qq[g * 4 + cc];
        }
    __syncthreads();
    {
        int col = tid & 127, which = tid >> 7;
        const float* src = which ? redQ : redS;
        float a = 0.f;
#pragma unroll
        for (int t = 0; t < 16; t++) a += src[t * 128 + col];
        atomicAdd(&g_s2[which * K2 + n0 + col], a);
    }
}

__global__ void k_fin2(const float* __restrict__ g2, const float* __restrict__ be2, float invN) {
    int k = threadIdx.x;
    float mu  = g_s2[k] * invN;
    float var = g_s2[K2 + k] * invN - mu * mu;
    float a = g2[k] * rsqrtf(var + 1e-5f);
    g_bn2[k] = a;
    g_bn2[K2 + k] = fmaf(-mu, a, be2[k]);
}

// ---------- pooling: pooled[b,k,c] += attn*x ; gp[b,k] += attn ----------
__global__ __launch_bounds__(256) void k_pool(const float* __restrict__ x,
                                              float* __restrict__ gp_out, int L) {
    __shared__ float Att[32][64];
    __shared__ __align__(16) float Xs[32][32];
    __shared__ float bn2s[2][64];
    int b = blockIdx.x;
    int k0 = blockIdx.y * 64;
    int lsl = L >> 3;
    size_t pbase = (size_t)b * L + (size_t)blockIdx.z * lsl;
    int tid = threadIdx.x;
    if (tid < 64) { bn2s[0][tid] = g_bn2[k0 + tid]; bn2s[1][tid] = g_bn2[K2 + k0 + tid]; }
    int kq = tid >> 2, tx = tid & 3;
    u64 acc[4] = {0ull, 0ull, 0ull, 0ull};
    float gpl = 0.f;
    for (int lc = 0; lc < lsl; lc += 32) {
        __syncthreads();
        for (int i = tid; i < 32 * 16; i += 256) {
            int r = i >> 4, c4 = (i & 15) * 4;
            float4 v = *(const float4*)&g_att[(pbase + lc + r) * K2 + k0 + c4];
            Att[r][c4]     = fmaxf(fmaf(bn2s[0][c4],     v.x, bn2s[1][c4]),     0.f);
            Att[r][c4 + 1] = fmaxf(fmaf(bn2s[0][c4 + 1], v.y, bn2s[1][c4 + 1]), 0.f);
            Att[r][c4 + 2] = fmaxf(fmaf(bn2s[0][c4 + 2], v.z, bn2s[1][c4 + 2]), 0.f);
            Att[r][c4 + 3] = fmaxf(fmaf(bn2s[0][c4 + 3], v.w, bn2s[1][c4 + 3]), 0.f);
        }
        for (int i = tid; i < 32 * 8; i += 256) {
            int r = i >> 3, c4 = (i & 7) * 4;
            *(float4*)&Xs[r][c4] = *(const float4*)&x[(pbase + lc + r) * CIN + c4];
        }
        __syncthreads();
#pragma unroll 4
        for (int l = 0; l < 32; l++) {
            float a = Att[l][kq];
            if (tx == 0) gpl += a;
            u64 ap = pk2(a, a);
#pragma unroll
            for (int j = 0; j < 4; j++) {
                u64 xp = *(const u64*)&Xs[l][tx * 8 + 2 * j];
                fma2(acc[j], ap, xp);
            }
        }
    }
    float* pd = &g_pooled[((size_t)b * K2 + k0 + kq) * CIN + tx * 8];
#pragma unroll
    for (int j = 0; j < 4; j++) {
        float2 f = upk2(acc[j]);
        atomicAdd(&pd[2 * j], f.x);
        atomicAdd(&pd[2 * j + 1], f.y);
    }
    if (tx == 0) atomicAdd(&gp_out[b * K2 + kq + k0], gpl);
}

// ---------- FC: resraw[b][j] = pooled[b]·wf[j]/L + bf[j] ----------
__global__ __launch_bounds__(256) void k_fc(const float* __restrict__ wf,
                                            const float* __restrict__ bf,
                                            int B, float invL) {
    int j = blockIdx.x;
    int tid = threadIdx.x;
    const float* wrow = wf + (size_t)j * (K2 * CIN);
    float acc[MAXB];
#pragma unroll
    for (int b = 0; b < MAXB; b++) acc[b] = 0.f;
    for (int i = tid; i < K2 * CIN; i += 256) {
        float w = wrow[i];
#pragma unroll
        for (int b = 0; b < MAXB; b++)
            if (b < B) acc[b] += w * g_pooled[(size_t)b * (K2 * CIN) + i];
    }
    __shared__ float red[8][MAXB];
    int lane = tid & 31, w = tid >> 5;
#pragma unroll
    for (int b = 0; b < MAXB; b++) {
        float v = acc[b];
#pragma unroll
        for (int o = 16; o; o >>= 1) v += __shfl_down_sync(0xffffffffu, v, o);
        if (lane == 0) red[w][b] = v;
    }
    __syncthreads();
    if (tid < B) {
        float ssum = 0.f;
        for (int i = 0; i < 8; i++) ssum += red[i][tid];
        g_resraw[tid * FCD + j] = fmaf(ssum, invL, bf[j]);
    }
}

// ---------- final: BN over B, L2 normalize, lengths ----------
__global__ void k_final(float* __restrict__ outp, const float* __restrict__ gf,
                        const float* __restrict__ bef, int B, int L) {
    int j = threadIdx.x;  // 256 threads
    __shared__ float rows[MAXB];
    if (j < B) rows[j] = 0.f;
    __syncthreads();
    float v[MAXB];
    float s = 0.f, q = 0.f;
    for (int b = 0; b < B; b++) {
        v[b] = g_resraw[b * FCD + j];
        s += v[b]; q += v[b] * v[b];
    }
    float invB = 1.f / (float)B;
    float mu = s * invB;
    float var = q * invB - mu * mu;
    float a = gf[j] * rsqrtf(var + 1e-5f);
    float c = fmaf(-mu, a, bef[j]);
    for (int b = 0; b < B; b++) {
        v[b] = fmaf(a, v[b], c);
        atomicAdd(&rows[b], v[b] * v[b]);
    }
    __syncthreads();
    for (int b = 0; b < B; b++)
        outp[b * FCD + j] = v[b] / fmaxf(sqrtf(rows[b]), 1e-12f);
    if (j < B) outp[B * FCD + B * K2 + j] = (float)L;
}

// ---------- launch ----------
extern "C" void kernel_launch(void* const* d_in, const int* in_sizes, int n_in,
                              void* d_out, int out_size) {
    const float* x   = (const float*)d_in[0];
    const float* w1  = (const float*)d_in[1];
    const float* b1  = (const float*)d_in[2];
    const float* g1  = (const float*)d_in[3];
    const float* be1 = (const float*)d_in[4];
    const float* w2  = (const float*)d_in[5];
    const float* b2  = (const float*)d_in[6];
    const float* g2  = (const float*)d_in[7];
    const float* be2 = (const float*)d_in[8];
    const float* wf  = (const float*)d_in[9];
    const float* bf  = (const float*)d_in[10];
    const float* gf  = (const float*)d_in[11];
    const float* bef = (const float*)d_in[12];
    float* outp = (float*)d_out;

    int N = in_sizes[0] / CIN;
    int B = out_size / (FCD + K2 + 1);
    int L = N / B;
    float invN = 1.f / (float)N;
    float invL = 1.f / (float)L;

    k_zero<<<(B * K2 * CIN + 255) / 256, 256>>>(outp, B);
    k_prep<<<(K2 * K1 + 255) / 256, 256>>>(w2);
    k_gemm1<<<N / 256, 256>>>(x, w1, b1, N);
    k_stats1<<<dim3(32, K1), 256>>>(N);
    k_fin1<<<1, K1>>>(g1, be1, invN);
    k_gemm2<<<dim3(K2 / 128, N / 128), 256>>>(b2, N);
    k_fin2<<<1, K2>>>(g2, be2, invN);
    k_pool<<<dim3(B, K2 / 64, 8), 256>>>(x, outp + B * FCD, L);
    k_fc<<<FCD, 256>>>(wf, bf, B, invL);
    k_final<<<1, FCD>>>(outp, gf, bef, B, L);
}

// round 5
// speedup vs baseline: 1.4312x; 1.0018x over previous
#include <cuda_runtime.h>
#include <cuda_bf16.h>
#include <cstdint>
#include <cstddef>

#define CIN 32
#define K1  128
#define K2  512
#define FCD 256
#define MAXN 524288
#define MAXB 16

typedef unsigned long long u64;

// ---------- scratch (device globals; no runtime allocation) ----------
__device__ float g_hT[(size_t)K1 * MAXN];     // h raw, transposed [K1][N]
__device__ float g_att[(size_t)MAXN * K2];    // att raw (pre-BN2) [N][K2], fp32
__device__ float g_w2t[K2 * K1];              // w2 transposed [K1][K2]
__device__ float g_s1[2 * K1];
__device__ float g_bn1[2 * K1];               // a1, c1
__device__ float g_s2[2 * K2];
__device__ float g_bn2[2 * K2];               // a2, c2
__device__ float g_pooled[MAXB * K2 * CIN];
__device__ float g_resraw[MAXB * FCD];

// ---------- packed f32x2 helpers ----------
__device__ __forceinline__ u64 pk2(float lo, float hi) {
    u64 r; asm("mov.b64 %0, {%1, %2};" : "=l"(r) : "f"(lo), "f"(hi)); return r;
}
__device__ __forceinline__ void fma2(u64 &d, u64 a, u64 b) {
    asm("fma.rn.f32x2 %0, %1, %2, %0;" : "+l"(d) : "l"(a), "l"(b));
}
__device__ __forceinline__ float2 upk2(u64 v) {
    float lo, hi; asm("mov.b64 {%0, %1}, %2;" : "=f"(lo), "=f"(hi) : "l"(v));
    return make_float2(lo, hi);
}
__device__ __forceinline__ void cpasync16(uint32_t dst, const void* src) {
    asm volatile("cp.async.cg.shared.global [%0], [%1], 16;" :: "r"(dst), "l"(src));
}

// ---------- zero accumulators + gp region of out ----------
__global__ void k_zero(float* outp, int B) {
    int i = blockIdx.x * blockDim.x + threadIdx.x;
    if (i < B * K2 * CIN) g_pooled[i] = 0.f;
    if (i < 2 * K1) g_s1[i] = 0.f;
    if (i < 2 * K2) g_s2[i] = 0.f;
    if (i < B * K2) outp[B * FCD + i] = 0.f;
}

// ---------- transpose w2 ----------
__global__ void k_prep(const float* __restrict__ w2) {
    int i = blockIdx.x * blockDim.x + threadIdx.x;
    if (i < K2 * K1) { int n = i / K1, k = i % K1; g_w2t[k * K2 + n] = w2[i]; }
}

// ---------- GEMM1 (f32x2): hT[k][p] = x[p]·w1[k] + b1[k] ----------
__global__ __launch_bounds__(256) void k_gemm1(const float* __restrict__ x,
                                               const float* __restrict__ w1,
                                               const float* __restrict__ b1, int N) {
    __shared__ __align__(16) float w1s[K1 * CIN];
    int tid = threadIdx.x;
    for (int i = tid; i < K1 * CIN; i += 256) w1s[i] = w1[i];
    size_t p = (size_t)blockIdx.x * 256 + tid;
    u64 xp2[16];
    const float4* xp = (const float4*)(x + p * CIN);
#pragma unroll
    for (int q = 0; q < 8; q++) {
        float4 v = xp[q];
        xp2[2*q]   = pk2(v.x, v.y);
        xp2[2*q+1] = pk2(v.z, v.w);
    }
    __syncthreads();
#pragma unroll 4
    for (int k = 0; k < K1; k++) {
        const u64* wr = (const u64*)(w1s + k * CIN);
        u64 a = 0ull;
#pragma unroll
        for (int q = 0; q < 16; q++) fma2(a, xp2[q], wr[q]);
        float2 f = upk2(a);
        g_hT[(size_t)k * N + p] = f.x + f.y + b1[k];
    }
}

// ---------- BN1 stats over hT rows ----------
__global__ __launch_bounds__(256) void k_stats1(int N) {
    int k = blockIdx.y;
    int per = N >> 5;
    const float* row = g_hT + (size_t)k * N + (size_t)blockIdx.x * per;
    float s = 0.f, q = 0.f;
    for (int i = threadIdx.x * 4; i < per; i += 1024) {
        float4 v = *(const float4*)(row + i);
        s += v.x + v.y + v.z + v.w;
        q += v.x*v.x + v.y*v.y + v.z*v.z + v.w*v.w;
    }
#pragma unroll
    for (int o = 16; o; o >>= 1) {
        s += __shfl_down_sync(0xffffffffu, s, o);
        q += __shfl_down_sync(0xffffffffu, q, o);
    }
    __shared__ float ws[8], wq[8];
    int w = threadIdx.x >> 5;
    if ((threadIdx.x & 31) == 0) { ws[w] = s; wq[w] = q; }
    __syncthreads();
    if (threadIdx.x == 0) {
        float S = 0.f, Q = 0.f;
        for (int i = 0; i < 8; i++) { S += ws[i]; Q += wq[i]; }
        atomicAdd(&g_s1[k], S); atomicAdd(&g_s1[K1 + k], Q);
    }
}

__global__ void k_fin1(const float* __restrict__ g1, const float* __restrict__ be1, float invN) {
    int k = threadIdx.x;
    float mu  = g_s1[k] * invN;
    float var = g_s1[K1 + k] * invN - mu * mu;
    float a = g1[k] * rsqrtf(var + 1e-5f);
    g_bn1[k] = a;
    g_bn1[K1 + k] = fmaf(-mu, a, be1[k]);
}

// ---------- GEMM2: att = relu(bn1(h))·w2 + b2 (fp32 out), fused BN2 stats ----------
// grid: (K2/128 fast, N/128 slow) so same-p blocks share A tiles in L2.
__global__ __launch_bounds__(256, 2) void k_gemm2(const float* __restrict__ b2, int N) {
    __shared__ __align__(16) float As[32][128];
    __shared__ __align__(16) float Bs[2][32][128];
    int tid = threadIdx.x;
    int tx = tid & 15, ty = tid >> 4;
    int n0 = blockIdx.x * 128;
    size_t p0 = (size_t)blockIdx.y * 128;

    int lk[4], lm[4];
#pragma unroll
    for (int q = 0; q < 4; q++) { int f = tid + 256 * q; lk[q] = f >> 5; lm[q] = (f & 31) * 4; }

    u64 acc[4][8];
#pragma unroll
    for (int mp = 0; mp < 4; mp++)
#pragma unroll
        for (int c = 0; c < 8; c++) acc[mp][c] = 0ull;

    // prologue: stage 0
    {
        uint32_t bs0 = (uint32_t)__cvta_generic_to_shared(&Bs[0][0][0]);
#pragma unroll
        for (int q = 0; q < 4; q++)
            cpasync16(bs0 + (uint32_t)(lk[q] * 128 + lm[q]) * 4,
                      &g_w2t[(size_t)lk[q] * K2 + n0 + lm[q]]);
        asm volatile("cp.async.commit_group;\n" ::: "memory");
        float4 Ar[4];
#pragma unroll
        for (int q = 0; q < 4; q++)
            Ar[q] = *(const float4*)&g_hT[(size_t)lk[q] * N + p0 + lm[q]];
#pragma unroll
        for (int q = 0; q < 4; q++) {
            int kg = lk[q];
            float a1 = g_bn1[kg], c1 = g_bn1[K1 + kg];
            float4 v = Ar[q];
            v.x = fmaxf(fmaf(a1, v.x, c1), 0.f);
            v.y = fmaxf(fmaf(a1, v.y, c1), 0.f);
            v.z = fmaxf(fmaf(a1, v.z, c1), 0.f);
            v.w = fmaxf(fmaf(a1, v.w, c1), 0.f);
            *(float4*)&As[lk[q]][lm[q]] = v;
        }
        asm volatile("cp.async.wait_group 0;\n" ::: "memory");
    }
    __syncthreads();

    float4 Ar[4];
    for (int kc = 0; kc < 4; kc++) {
        int kb = (kc + 1) * 32;
        if (kc < 3) {
            uint32_t bsn = (uint32_t)__cvta_generic_to_shared(&Bs[(kc + 1) & 1][0][0]);
#pragma unroll
            for (int q = 0; q < 4; q++)
                cpasync16(bsn + (uint32_t)(lk[q] * 128 + lm[q]) * 4,
                          &g_w2t[(size_t)(kb + lk[q]) * K2 + n0 + lm[q]]);
            asm volatile("cp.async.commit_group;\n" ::: "memory");
#pragma unroll
            for (int q = 0; q < 4; q++)
                Ar[q] = *(const float4*)&g_hT[(size_t)(kb + lk[q]) * N + p0 + lm[q]];
        }
        const float (*Bc)[128] = Bs[kc & 1];
#pragma unroll 2
        for (int kk = 0; kk < 32; kk++) {
            u64 ap[4];
#pragma unroll
            for (int mp = 0; mp < 4; mp++)
                ap[mp] = *(const u64*)&As[kk][ty * 8 + 2 * mp];
            float4 bv0 = *(const float4*)&Bc[kk][4 * tx];
            float4 bv1 = *(const float4*)&Bc[kk][64 + 4 * tx];
            u64 bp[8];
            bp[0] = pk2(bv0.x, bv0.x); bp[1] = pk2(bv0.y, bv0.y);
            bp[2] = pk2(bv0.z, bv0.z); bp[3] = pk2(bv0.w, bv0.w);
            bp[4] = pk2(bv1.x, bv1.x); bp[5] = pk2(bv1.y, bv1.y);
            bp[6] = pk2(bv1.z, bv1.z); bp[7] = pk2(bv1.w, bv1.w);
#pragma unroll
            for (int mp = 0; mp < 4; mp++)
#pragma unroll
                for (int c = 0; c < 8; c++) fma2(acc[mp][c], ap[mp], bp[c]);
        }
        __syncthreads();
        if (kc < 3) {
#pragma unroll
            for (int q = 0; q < 4; q++) {
                int kg = kb + lk[q];
                float a1 = g_bn1[kg], c1 = g_bn1[K1 + kg];
                float4 v = Ar[q];
                v.x = fmaxf(fmaf(a1, v.x, c1), 0.f);
                v.y = fmaxf(fmaf(a1, v.y, c1), 0.f);
                v.z = fmaxf(fmaf(a1, v.z, c1), 0.f);
                v.w = fmaxf(fmaf(a1, v.w, c1), 0.f);
                *(float4*)&As[lk[q]][lm[q]] = v;
            }
            asm volatile("cp.async.wait_group 0;\n" ::: "memory");
            __syncthreads();
        }
    }

    // epilogue: +b2, fp32 store, accumulate BN2 stats on stored values
    float bb[8];
#pragma unroll
    for (int g = 0; g < 2; g++)
#pragma unroll
        for (int cc = 0; cc < 4; cc++) bb[g * 4 + cc] = b2[n0 + 64 * g + 4 * tx + cc];

    float s[8], qq[8];
#pragma unroll
    for (int c = 0; c < 8; c++) { s[c] = 0.f; qq[c] = 0.f; }

#pragma unroll
    for (int mp = 0; mp < 4; mp++) {
        float rv[2][8];
#pragma unroll
        for (int c = 0; c < 8; c++) {
            float2 f = upk2(acc[mp][c]);
            rv[0][c] = f.x + bb[c];
            rv[1][c] = f.y + bb[c];
            s[c] += rv[0][c] + rv[1][c];
            qq[c] += rv[0][c] * rv[0][c] + rv[1][c] * rv[1][c];
        }
#pragma unroll
        for (int rr = 0; rr < 2; rr++) {
            size_t row = p0 + (size_t)(ty * 8 + 2 * mp + rr);
            float* orow = g_att + row * K2 + n0;
            float4 o0, o1;
            o0.x = rv[rr][0]; o0.y = rv[rr][1]; o0.z = rv[rr][2]; o0.w = rv[rr][3];
            o1.x = rv[rr][4]; o1.y = rv[rr][5]; o1.z = rv[rr][6]; o1.w = rv[rr][7];
            *(float4*)(orow + 4 * tx)      = o0;
            *(float4*)(orow + 64 + 4 * tx) = o1;
        }
    }

    // block-level reduce of stats over ty, then one atomic per (col, stat)
    __syncthreads();
    float* redS = &As[0][0];
    float* redQ = &Bs[0][0][0];
#pragma unroll
    for (int g = 0; g < 2; g++)
#pragma unroll
        for (int cc = 0; cc < 4; cc++) {
            int col = 64 * g + 4 * tx + cc;
            redS[ty * 128 + col] = s[g * 4 + cc];
            redQ[ty * 128 + col] = qq[g * 4 + cc];
        }
    __syncthreads();
    {
        int col = tid & 127, which = tid >> 7;
        const float* src = which ? redQ : redS;
        float a = 0.f;
#pragma unroll
        for (int t = 0; t < 16; t++) a += src[t * 128 + col];
        atomicAdd(&g_s2[which * K2 + n0 + col], a);
    }
}

__global__ void k_fin2(const float* __restrict__ g2, const float* __restrict__ be2, float invN) {
    int k = threadIdx.x;
    float mu  = g_s2[k] * invN;
    float var = g_s2[K2 + k] * invN - mu * mu;
    float a = g2[k] * rsqrtf(var + 1e-5f);
    g_bn2[k] = a;
    g_bn2[K2 + k] = fmaf(-mu, a, be2[k]);
}

// ---------- pooling: pooled[b,k,c] += attn*x ; gp[b,k] += attn ----------
__global__ __launch_bounds__(256) void k_pool(const float* __restrict__ x,
                                              float* __restrict__ gp_out, int L) {
    __shared__ float Att[32][64];
    __shared__ __align__(16) float Xs[32][32];
    __shared__ float bn2s[2][64];
    int b = blockIdx.x;
    int k0 = blockIdx.y * 64;
    int lsl = L >> 3;
    size_t pbase = (size_t)b * L + (size_t)blockIdx.z * lsl;
    int tid = threadIdx.x;
    if (tid < 64) { bn2s[0][tid] = g_bn2[k0 + tid]; bn2s[1][tid] = g_bn2[K2 + k0 + tid]; }
    int kq = tid >> 2, tx = tid & 3;
    u64 acc[4] = {0ull, 0ull, 0ull, 0ull};
    float gpl = 0.f;
    for (int lc = 0; lc < lsl; lc += 32) {
        __syncthreads();
        for (int i = tid; i < 32 * 16; i += 256) {
            int r = i >> 4, c4 = (i & 15) * 4;
            float4 v = *(const float4*)&g_att[(pbase + lc + r) * K2 + k0 + c4];
            Att[r][c4]     = fmaxf(fmaf(bn2s[0][c4],     v.x, bn2s[1][c4]),     0.f);
            Att[r][c4 + 1] = fmaxf(fmaf(bn2s[0][c4 + 1], v.y, bn2s[1][c4 + 1]), 0.f);
            Att[r][c4 + 2] = fmaxf(fmaf(bn2s[0][c4 + 2], v.z, bn2s[1][c4 + 2]), 0.f);
            Att[r][c4 + 3] = fmaxf(fmaf(bn2s[0][c4 + 3], v.w, bn2s[1][c4 + 3]), 0.f);
        }
        for (int i = tid; i < 32 * 8; i += 256) {
            int r = i >> 3, c4 = (i & 7) * 4;
            *(float4*)&Xs[r][c4] = *(const float4*)&x[(pbase + lc + r) * CIN + c4];
        }
        __syncthreads();
#pragma unroll 4
        for (int l = 0; l < 32; l++) {
            float a = Att[l][kq];
            if (tx == 0) gpl += a;
            u64 ap = pk2(a, a);
#pragma unroll
            for (int j = 0; j < 4; j++) {
                u64 xp = *(const u64*)&Xs[l][tx * 8 + 2 * j];
                fma2(acc[j], ap, xp);
            }
        }
    }
    float* pd = &g_pooled[((size_t)b * K2 + k0 + kq) * CIN + tx * 8];
#pragma unroll
    for (int j = 0; j < 4; j++) {
        float2 f = upk2(acc[j]);
        atomicAdd(&pd[2 * j], f.x);
        atomicAdd(&pd[2 * j + 1], f.y);
    }
    if (tx == 0) atomicAdd(&gp_out[b * K2 + kq + k0], gpl);
}

// ---------- FC: resraw[b][j] = pooled[b]·wf[j]/L + bf[j] ----------
__global__ __launch_bounds__(256) void k_fc(const float* __restrict__ wf,
                                            const float* __restrict__ bf,
                                            int B, float invL) {
    int j = blockIdx.x;
    int tid = threadIdx.x;
    const float* wrow = wf + (size_t)j * (K2 * CIN);
    float acc[MAXB];
#pragma unroll
    for (int b = 0; b < MAXB; b++) acc[b] = 0.f;
    for (int i = tid; i < K2 * CIN; i += 256) {
        float w = wrow[i];
#pragma unroll
        for (int b = 0; b < MAXB; b++)
            if (b < B) acc[b] += w * g_pooled[(size_t)b * (K2 * CIN) + i];
    }
    __shared__ float red[8][MAXB];
    int lane = tid & 31, w = tid >> 5;
#pragma unroll
    for (int b = 0; b < MAXB; b++) {
        float v = acc[b];
#pragma unroll
        for (int o = 16; o; o >>= 1) v += __shfl_down_sync(0xffffffffu, v, o);
        if (lane == 0) red[w][b] = v;
    }
    __syncthreads();
    if (tid < B) {
        float ssum = 0.f;
        for (int i = 0; i < 8; i++) ssum += red[i][tid];
        g_resraw[tid * FCD + j] = fmaf(ssum, invL, bf[j]);
    }
}

// ---------- final: BN over B, L2 normalize, lengths ----------
__global__ void k_final(float* __restrict__ outp, const float* __restrict__ gf,
                        const float* __restrict__ bef, int B, int L) {
    int j = threadIdx.x;  // 256 threads
    __shared__ float rows[MAXB];
    if (j < B) rows[j] = 0.f;
    __syncthreads();
    float v[MAXB];
    float s = 0.f, q = 0.f;
    for (int b = 0; b < B; b++) {
        v[b] = g_resraw[b * FCD + j];
        s += v[b]; q += v[b] * v[b];
    }
    float invB = 1.f / (float)B;
    float mu = s * invB;
    float var = q * invB - mu * mu;
    float a = gf[j] * rsqrtf(var + 1e-5f);
    float c = fmaf(-mu, a, bef[j]);
    for (int b = 0; b < B; b++) {
        v[b] = fmaf(a, v[b], c);
        atomicAdd(&rows[b], v[b] * v[b]);
    }
    __syncthreads();
    for (int b = 0; b < B; b++)
        outp[b * FCD + j] = v[b] / fmaxf(sqrtf(rows[b]), 1e-12f);
    if (j < B) outp[B * FCD + B * K2 + j] = (float)L;
}

// ---------- launch ----------
extern "C" void kernel_launch(void* const* d_in, const int* in_sizes, int n_in,
                              void* d_out, int out_size) {
    const float* x   = (const float*)d_in[0];
    const float* w1  = (const float*)d_in[1];
    const float* b1  = (const float*)d_in[2];
    const float* g1  = (const float*)d_in[3];
    const float* be1 = (const float*)d_in[4];
    const float* w2  = (const float*)d_in[5];
    const float* b2  = (const float*)d_in[6];
    const float* g2  = (const float*)d_in[7];
    const float* be2 = (const float*)d_in[8];
    const float* wf  = (const float*)d_in[9];
    const float* bf  = (const float*)d_in[10];
    const float* gf  = (const float*)d_in[11];
    const float* bef = (const float*)d_in[12];
    float* outp = (float*)d_out;

    int N = in_sizes[0] / CIN;
    int B = out_size / (FCD + K2 + 1);
    int L = N / B;
    float invN = 1.f / (float)N;
    float invL = 1.f / (float)L;

    k_zero<<<(B * K2 * CIN + 255) / 256, 256>>>(outp, B);
    k_prep<<<(K2 * K1 + 255) / 256, 256>>>(w2);
    k_gemm1<<<N / 256, 256>>>(x, w1, b1, N);
    k_stats1<<<dim3(32, K1), 256>>>(N);
    k_fin1<<<1, K1>>>(g1, be1, invN);
    k_gemm2<<<dim3(K2 / 128, N / 128), 256>>>(b2, N);
    k_fin2<<<1, K2>>>(g2, be2, invN);
    k_pool<<<dim3(B, K2 / 64, 8), 256>>>(x, outp + B * FCD, L);
    k_fc<<<FCD, 256>>>(wf, bf, B, invL);
    k_final<<<1, FCD>>>(outp, gf, bef, B, L);
}

// round 7
// speedup vs baseline: 1.6728x; 1.1689x over previous
#include <cuda_runtime.h>
#include <cuda_bf16.h>
#include <cstdint>
#include <cstddef>
#include <cstring>

#define CIN 32
#define K1  128
#define K2  512
#define FCD 256
#define MAXN 524288
#define MAXB 16

typedef unsigned long long u64;

__device__ float g_hT[(size_t)K1 * MAXN];
__device__ float g_att[(size_t)MAXN * K2];
__device__ uint4 g_Ah4[(size_t)MAXN * 16];   // bf16 hi, row-major [p][128]
__device__ uint4 g_Al4[(size_t)MAXN * 16];   // bf16 lo
__device__ uint4 g_Bh4[K2 * 16];             // w2 hi, [n][128]
__device__ uint4 g_Bl4[K2 * 16];
__device__ float g_s1[2 * K1];
__device__ float g_bn1[2 * K1];
__device__ float g_s2[2 * K2];
__device__ float g_bn2[2 * K2];
__device__ float g_pooled[MAXB * K2 * CIN];
__device__ float g_resraw[MAXB * FCD];

__device__ __forceinline__ u64 pk2(float lo, float hi) {
    u64 r; asm("mov.b64 %0, {%1, %2};" : "=l"(r) : "f"(lo), "f"(hi)); return r;
}
__device__ __forceinline__ void fma2(u64 &d, u64 a, u64 b) {
    asm("fma.rn.f32x2 %0, %1, %2, %0;" : "+l"(d) : "l"(a), "l"(b));
}
__device__ __forceinline__ float2 upk2(u64 v) {
    float lo, hi; asm("mov.b64 {%0, %1}, %2;" : "=f"(lo), "=f"(hi) : "l"(v));
    return make_float2(lo, hi);
}
__device__ __forceinline__ uint32_t smem_u32(const void* p) {
    uint32_t a;
    asm("{ .reg .u64 t; cvta.to.shared.u64 t, %1; cvt.u32.u64 %0, t; }" : "=r"(a) : "l"(p));
    return a;
}
__device__ __forceinline__ void cpasync16(uint32_t dst, const void* src) {
    asm volatile("cp.async.cg.shared.global [%0], [%1], 16;" :: "r"(dst), "l"(src));
}
#define CP_COMMIT() asm volatile("cp.async.commit_group;" ::: "memory")

__device__ __forceinline__ void ldm4(uint32_t* r, uint32_t a) {
    asm volatile("ldmatrix.sync.aligned.m8n8.x4.shared.b16 {%0,%1,%2,%3}, [%4];"
        : "=r"(r[0]), "=r"(r[1]), "=r"(r[2]), "=r"(r[3]) : "r"(a));
}
__device__ __forceinline__ void mma16816(float* d, const uint32_t* a, uint32_t b0, uint32_t b1) {
    asm volatile("mma.sync.aligned.m16n8k16.row.col.f32.bf16.bf16.f32 "
        "{%0,%1,%2,%3}, {%4,%5,%6,%7}, {%8,%9}, {%0,%1,%2,%3};"
        : "+f"(d[0]), "+f"(d[1]), "+f"(d[2]), "+f"(d[3])
        : "r"(a[0]), "r"(a[1]), "r"(a[2]), "r"(a[3]), "r"(b0), "r"(b1));
}

__device__ __forceinline__ void split8(const float* v, uint32_t* hw, uint32_t* lw) {
#pragma unroll
    for (int j = 0; j < 4; j++) {
        float f0 = v[2 * j], f1 = v[2 * j + 1];
        __nv_bfloat162 h2 = __floats2bfloat162_rn(f0, f1);
        float r0 = f0 - __low2float(h2);
        float r1 = f1 - __high2float(h2);
        __nv_bfloat162 l2 = __floats2bfloat162_rn(r0, r1);
        memcpy(&hw[j], &h2, 4); memcpy(&lw[j], &l2, 4);
    }
}

__global__ void k_zero(float* outp, int B) {
    int i = blockIdx.x * blockDim.x + threadIdx.x;
    if (i < B * K2 * CIN) g_pooled[i] = 0.f;
    if (i < 2 * K1) g_s1[i] = 0.f;
    if (i < 2 * K2) g_s2[i] = 0.f;
    if (i < B * K2) outp[B * FCD + i] = 0.f;
}

__global__ void k_prepb(const float* __restrict__ w2) {
    int i = blockIdx.x * 256 + threadIdx.x;
    if (i >= K2 * 16) return;
    int n = i >> 4, q = i & 15;
    float v[8];
    *(float4*)v       = *(const float4*)(w2 + (size_t)n * 128 + q * 8);
    *(float4*)(v + 4) = *(const float4*)(w2 + (size_t)n * 128 + q * 8 + 4);
    uint32_t hw[4], lw[4];
    split8(v, hw, lw);
    g_Bh4[n * 16 + q] = make_uint4(hw[0], hw[1], hw[2], hw[3]);
    g_Bl4[n * 16 + q] = make_uint4(lw[0], lw[1], lw[2], lw[3]);
}

__global__ __launch_bounds__(256) void k_gemm1(const float* __restrict__ x,
                                               const float* __restrict__ w1,
                                               const float* __restrict__ b1, int N) {
    __shared__ __align__(16) float w1s[K1 * CIN];
    int tid = threadIdx.x;
    for (int i = tid; i < K1 * CIN; i += 256) w1s[i] = w1[i];
    size_t p = (size_t)blockIdx.x * 256 + tid;
    u64 xp2[16];
    const float4* xp = (const float4*)(x + p * CIN);
#pragma unroll
    for (int q = 0; q < 8; q++) {
        float4 v = xp[q];
        xp2[2 * q] = pk2(v.x, v.y); xp2[2 * q + 1] = pk2(v.z, v.w);
    }
    __syncthreads();
#pragma unroll 4
    for (int k = 0; k < K1; k++) {
        const u64* wr = (const u64*)(w1s + k * CIN);
        u64 a = 0ull;
#pragma unroll
        for (int q = 0; q < 16; q++) fma2(a, xp2[q], wr[q]);
        float2 f = upk2(a);
        g_hT[(size_t)k * N + p] = f.x + f.y + b1[k];
    }
}

__global__ __launch_bounds__(256) void k_stats1(int N) {
    int k = blockIdx.y;
    int per = N >> 5;
    const float* row = g_hT + (size_t)k * N + (size_t)blockIdx.x * per;
    float s = 0.f, q = 0.f;
    for (int i = threadIdx.x * 4; i < per; i += 1024) {
        float4 v = *(const float4*)(row + i);
        s += v.x + v.y + v.z + v.w;
        q += v.x * v.x + v.y * v.y + v.z * v.z + v.w * v.w;
    }
#pragma unroll
    for (int o = 16; o; o >>= 1) {
        s += __shfl_down_sync(0xffffffffu, s, o);
        q += __shfl_down_sync(0xffffffffu, q, o);
    }
    __shared__ float ws[8], wq[8];
    int w = threadIdx.x >> 5;
    if ((threadIdx.x & 31) == 0) { ws[w] = s; wq[w] = q; }
    __syncthreads();
    if (threadIdx.x == 0) {
        float S = 0.f, Q = 0.f;
        for (int i = 0; i < 8; i++) { S += ws[i]; Q += wq[i]; }
        atomicAdd(&g_s1[k], S); atomicAdd(&g_s1[K1 + k], Q);
    }
}

__global__ void k_fin1(const float* __restrict__ g1, const float* __restrict__ be1, float invN) {
    int k = threadIdx.x;
    float mu = g_s1[k] * invN;
    float var = g_s1[K1 + k] * invN - mu * mu;
    float a = g1[k] * rsqrtf(var + 1e-5f);
    g_bn1[k] = a;
    g_bn1[K1 + k] = fmaf(-mu, a, be1[k]);
}

// relu(bn1(hT)) -> row-major bf16 hi/lo [p][128]
__global__ __launch_bounds__(256) void k_conv(int N) {
    __shared__ float st[64][129];
    int mt = blockIdx.x, tid = threadIdx.x;
    size_t p0 = (size_t)mt * 128;
    for (int pass = 0; pass < 2; pass++) {
        int k0 = pass * 64;
        for (int i = tid; i < 64 * 32; i += 256) {
            int k = i >> 5, c4 = (i & 31) * 4;
            float4 v = *(const float4*)&g_hT[(size_t)(k0 + k) * N + p0 + c4];
            float a1 = g_bn1[k0 + k], c1 = g_bn1[K1 + k0 + k];
            st[k][c4]     = fmaxf(fmaf(a1, v.x, c1), 0.f);
            st[k][c4 + 1] = fmaxf(fmaf(a1, v.y, c1), 0.f);
            st[k][c4 + 2] = fmaxf(fmaf(a1, v.z, c1), 0.f);
            st[k][c4 + 3] = fmaxf(fmaf(a1, v.w, c1), 0.f);
        }
        __syncthreads();
        for (int i = tid; i < 128 * 8; i += 256) {
            int q = i & 7, m = i >> 3;
            float v[8];
#pragma unroll
            for (int j = 0; j < 8; j++) v[j] = st[q * 8 + j][m];
            uint32_t hw[4], lw[4];
            split8(v, hw, lw);
            size_t idx = (p0 + m) * 16 + pass * 8 + q;
            g_Ah4[idx] = make_uint4(hw[0], hw[1], hw[2], hw[3]);
            g_Al4[idx] = make_uint4(lw[0], lw[1], lw[2], lw[3]);
        }
        __syncthreads();
    }
}

// ---- GEMM2 via HMMA bf16x3: att = A·B^T + b2, fused BN2 stats ----
// smem: 2 stages x [Ah(10240) Al Bh Bl] = 81920, bias @81920 (512). total 82432.
#define STG_SZ 40960
#define SM_TOTAL 82432

__global__ __launch_bounds__(256, 2) void k_gemm2_mma(const float* __restrict__ b2, int N) {
    extern __shared__ char smem[];
    uint32_t sb = smem_u32(smem);
    int tid = threadIdx.x, lane = tid & 31, wid = tid >> 5;
    int wm = wid >> 1, wn = wid & 1;
    int nb = blockIdx.x;
    int n0 = nb * 128;
    size_t p0 = (size_t)blockIdx.y * 128;
    float* bs = (float*)(smem + 81920);
    if (tid < 128) bs[tid] = b2[n0 + tid];

    // copy one 32-k chunk (A+B, hi+lo) into a stage
    auto copy_chunk = [&](int ck, uint32_t stg) {
        for (int e = tid; e < 2048; e += 256) {
            int part = e >> 10, sub = (e >> 9) & 1;
            int r = (e & 511) >> 2, cc = e & 3;
            uint32_t dst = stg + (uint32_t)((part * 2 + sub) * 10240 + r * 80 + cc * 16);
            const char* base = part ? (sub ? (const char*)g_Bl4 : (const char*)g_Bh4)
                                    : (sub ? (const char*)g_Al4 : (const char*)g_Ah4);
            size_t row = part ? (size_t)(n0 + r) : (p0 + r);
            cpasync16(dst, base + row * 256 + ck * 64 + cc * 16);
        }
        CP_COMMIT();
    };
    copy_chunk(0, sb);
    copy_chunk(1, sb + STG_SZ);

    float acc[2][8][4];
#pragma unroll
    for (int mi = 0; mi < 2; mi++)
#pragma unroll
        for (int c = 0; c < 8; c++)
#pragma unroll
            for (int j = 0; j < 4; j++) acc[mi][c][j] = 0.f;

    uint32_t laneOff = (uint32_t)((lane & 15) * 80 + (lane >> 4) * 16);

    for (int c = 0; c < 4; c++) {
        if (c < 3) asm volatile("cp.async.wait_group 1;" ::: "memory");
        else       asm volatile("cp.async.wait_group 0;" ::: "memory");
        __syncthreads();
        uint32_t stg = sb + (uint32_t)(c & 1) * STG_SZ;
        uint32_t aBase = stg + (uint32_t)(wm * 32 * 80) + laneOff;
        uint32_t bBase = stg + 20480u + (uint32_t)(wn * 64 * 80) + laneOff;
#pragma unroll
        for (int ksl = 0; ksl < 2; ksl++) {
            uint32_t ah[2][4], al[2][4];
#pragma unroll
            for (int mi = 0; mi < 2; mi++) {
                ldm4(ah[mi], aBase + mi * 1280 + ksl * 32);
                ldm4(al[mi], aBase + 10240 + mi * 1280 + ksl * 32);
            }
#pragma unroll
            for (int nj = 0; nj < 4; nj++) {
                uint32_t bh[4], bl[4];
                ldm4(bh, bBase + nj * 1280 + ksl * 32);
                ldm4(bl, bBase + 10240 + nj * 1280 + ksl * 32);
#pragma unroll
                for (int mi = 0; mi < 2; mi++)
#pragma unroll
                    for (int s = 0; s < 2; s++) {
                        float* d = acc[mi][nj * 2 + s];
                        mma16816(d, ah[mi], bh[s], bh[s + 2]);
                        mma16816(d, ah[mi], bl[s], bl[s + 2]);
                        mma16816(d, al[mi], bh[s], bh[s + 2]);
                    }
            }
        }
        __syncthreads();
        if (c < 2) copy_chunk(c + 2, sb + (uint32_t)(c & 1) * STG_SZ);
    }

    // epilogue: stage tile (swizzled), then coalesced store + fused BN2 stats
    float* stgf = (float*)smem;
    int t4 = lane >> 2, t2 = 2 * (lane & 3);
#pragma unroll
    for (int mi = 0; mi < 2; mi++) {
        int mB = wm * 32 + mi * 16 + t4;
#pragma unroll
        for (int c = 0; c < 8; c++) {
            int nn = wn * 64 + c * 8 + t2;
            float* d = acc[mi][c];
            *(float2*)&stgf[mB * 128 + (nn ^ ((mB & 7) << 2))] = make_float2(d[0], d[1]);
            int m2 = mB + 8;
            *(float2*)&stgf[m2 * 128 + (nn ^ ((m2 & 7) << 2))] = make_float2(d[2], d[3]);
        }
    }
    __syncthreads();
#pragma unroll
    for (int it = 0; it < 16; it++) {
        int task = tid + it * 256;
        int rr = task >> 5, c4 = (task & 31) * 4;
        float4 v = *(const float4*)&stgf[rr * 128 + (c4 ^ ((rr & 7) << 2))];
        float4 bb = *(const float4*)&bs[c4];
        v.x += bb.x; v.y += bb.y; v.z += bb.z; v.w += bb.w;
        *(float4*)&g_att[(p0 + rr) * K2 + n0 + c4] = v;
    }
    {
        int col = tid & 127, half = tid >> 7;
        float bias = bs[col];
        float s = 0.f, q = 0.f;
        for (int r = half * 64; r < half * 64 + 64; r++) {
            float v = stgf[r * 128 + (col ^ ((r & 7) << 2))] + bias;
            s += v; q += v * v;
        }
        atomicAdd(&g_s2[n0 + col], s);
        atomicAdd(&g_s2[K2 + n0 + col], q);
    }
}

__global__ void k_fin2(const float* __restrict__ g2, const float* __restrict__ be2, float invN) {
    int k = threadIdx.x;
    float mu = g_s2[k] * invN;
    float var = g_s2[K2 + k] * invN - mu * mu;
    float a = g2[k] * rsqrtf(var + 1e-5f);
    g_bn2[k] = a;
    g_bn2[K2 + k] = fmaf(-mu, a, be2[k]);
}

__global__ __launch_bounds__(256) void k_pool(const float* __restrict__ x,
                                              float* __restrict__ gp_out, int L) {
    __shared__ float Att[32][64];
    __shared__ __align__(16) float Xs[32][32];
    __shared__ float bn2s[2][64];
    int b = blockIdx.x;
    int k0 = blockIdx.y * 64;
    int lsl = L >> 3;
    size_t pbase = (size_t)b * L + (size_t)blockIdx.z * lsl;
    int tid = threadIdx.x;
    if (tid < 64) { bn2s[0][tid] = g_bn2[k0 + tid]; bn2s[1][tid] = g_bn2[K2 + k0 + tid]; }
    int kq = tid >> 2, tx = tid & 3;
    u64 acc[4] = {0ull, 0ull, 0ull, 0ull};
    float gpl = 0.f;
    for (int lc = 0; lc < lsl; lc += 32) {
        __syncthreads();
        for (int i = tid; i < 32 * 16; i += 256) {
            int r = i >> 4, c4 = (i & 15) * 4;
            float4 v = *(const float4*)&g_att[(pbase + lc + r) * K2 + k0 + c4];
            Att[r][c4]     = fmaxf(fmaf(bn2s[0][c4],     v.x, bn2s[1][c4]),     0.f);
            Att[r][c4 + 1] = fmaxf(fmaf(bn2s[0][c4 + 1], v.y, bn2s[1][c4 + 1]), 0.f);
            Att[r][c4 + 2] = fmaxf(fmaf(bn2s[0][c4 + 2], v.z, bn2s[1][c4 + 2]), 0.f);
            Att[r][c4 + 3] = fmaxf(fmaf(bn2s[0][c4 + 3], v.w, bn2s[1][c4 + 3]), 0.f);
        }
        for (int i = tid; i < 32 * 8; i += 256) {
            int r = i >> 3, c4 = (i & 7) * 4;
            *(float4*)&Xs[r][c4] = *(const float4*)&x[(pbase + lc + r) * CIN + c4];
        }
        __syncthreads();
#pragma unroll 4
        for (int l = 0; l < 32; l++) {
            float a = Att[l][kq];
            if (tx == 0) gpl += a;
            u64 ap = pk2(a, a);
#pragma unroll
            for (int j = 0; j < 4; j++) {
                u64 xp = *(const u64*)&Xs[l][tx * 8 + 2 * j];
                fma2(acc[j], ap, xp);
            }
        }
    }
    float* pd = &g_pooled[((size_t)b * K2 + k0 + kq) * CIN + tx * 8];
#pragma unroll
    for (int j = 0; j < 4; j++) {
        float2 f = upk2(acc[j]);
        atomicAdd(&pd[2 * j], f.x);
        atomicAdd(&pd[2 * j + 1], f.y);
    }
    if (tx == 0) atomicAdd(&gp_out[b * K2 + kq + k0], gpl);
}

__global__ __launch_bounds__(256) void k_fc(const float* __restrict__ wf,
                                            const float* __restrict__ bf,
                                            int B, float invL) {
    int j = blockIdx.x, tid = threadIdx.x;
    const float* wrow = wf + (size_t)j * (K2 * CIN);
    float acc[MAXB];
#pragma unroll
    for (int b = 0; b < MAXB; b++) acc[b] = 0.f;
    for (int i = tid; i < K2 * CIN; i += 256) {
        float w = wrow[i];
#pragma unroll
        for (int b = 0; b < MAXB; b++)
            if (b < B) acc[b] += w * g_pooled[(size_t)b * (K2 * CIN) + i];
    }
    __shared__ float red[8][MAXB];
    int lane = tid & 31, w = tid >> 5;
#pragma unroll
    for (int b = 0; b < MAXB; b++) {
        float v = acc[b];
#pragma unroll
        for (int o = 16; o; o >>= 1) v += __shfl_down_sync(0xffffffffu, v, o);
        if (lane == 0) red[w][b] = v;
    }
    __syncthreads();
    if (tid < B) {
        float ssum = 0.f;
        for (int i = 0; i < 8; i++) ssum += red[i][tid];
        g_resraw[tid * FCD + j] = fmaf(ssum, invL, bf[j]);
    }
}

__global__ void k_final(float* __restrict__ outp, const float* __restrict__ gf,
                        const float* __restrict__ bef, int B, int L) {
    int j = threadIdx.x;
    __shared__ float rows[MAXB];
    if (j < B) rows[j] = 0.f;
    __syncthreads();
    float v[MAXB];
    float s = 0.f, q = 0.f;
    for (int b = 0; b < B; b++) {
        v[b] = g_resraw[b * FCD + j];
        s += v[b]; q += v[b] * v[b];
    }
    float invB = 1.f / (float)B;
    float mu = s * invB;
    float var = q * invB - mu * mu;
    float a = gf[j] * rsqrtf(var + 1e-5f);
    float c = fmaf(-mu, a, bef[j]);
    for (int b = 0; b < B; b++) {
        v[b] = fmaf(a, v[b], c);
        atomicAdd(&rows[b], v[b] * v[b]);
    }
    __syncthreads();
    for (int b = 0; b < B; b++)
        outp[b * FCD + j] = v[b] / fmaxf(sqrtf(rows[b]), 1e-12f);
    if (j < B) outp[B * FCD + B * K2 + j] = (float)L;
}

extern "C" void kernel_launch(void* const* d_in, const int* in_sizes, int n_in,
                              void* d_out, int out_size) {
    const float* x   = (const float*)d_in[0];
    const float* w1  = (const float*)d_in[1];
    const float* b1  = (const float*)d_in[2];
    const float* g1  = (const float*)d_in[3];
    const float* be1 = (const float*)d_in[4];
    const float* w2  = (const float*)d_in[5];
    const float* b2  = (const float*)d_in[6];
    const float* g2  = (const float*)d_in[7];
    const float* be2 = (const float*)d_in[8];
    const float* wf  = (const float*)d_in[9];
    const float* bf  = (const float*)d_in[10];
    const float* gf  = (const float*)d_in[11];
    const float* bef = (const float*)d_in[12];
    float* outp = (float*)d_out;

    int N = in_sizes[0] / CIN;
    int B = out_size / (FCD + K2 + 1);
    int L = N / B;
    float invN = 1.f / (float)N;
    float invL = 1.f / (float)L;

    cudaFuncSetAttribute(k_gemm2_mma, cudaFuncAttributeMaxDynamicSharedMemorySize, SM_TOTAL);

    k_zero<<<(B * K2 * CIN + 255) / 256, 256>>>(outp, B);
    k_prepb<<<(K2 * 16 + 255) / 256, 256>>>(w2);
    k_gemm1<<<N / 256, 256>>>(x, w1, b1, N);
    k_stats1<<<dim3(32, K1), 256>>>(N);
    k_fin1<<<1, K1>>>(g1, be1, invN);
    k_conv<<<N / 128, 256>>>(N);
    k_gemm2_mma<<<dim3(4, N / 128), 256, SM_TOTAL>>>(b2, N);
    k_fin2<<<1, K2>>>(g2, be2, invN);
    k_pool<<<dim3(B, K2 / 64, 8), 256>>>(x, outp + B * FCD, L);
    k_fc<<<FCD, 256>>>(wf, bf, B, invL);
    k_final<<<1, FCD>>>(outp, gf, bef, B, L);
}

// round 8
// speedup vs baseline: 1.8730x; 1.1196x over previous
#include <cuda_runtime.h>
#include <cuda_bf16.h>
#include <cstdint>
#include <cstddef>
#include <cstring>

#define CIN 32
#define K1  128
#define K2  512
#define FCD 256
#define MAXN 524288
#define MAXB 16

typedef unsigned long long u64;

__device__ float g_att[(size_t)MAXN * K2];
__device__ uint4 g_Ah4[(size_t)MAXN * 16];   // bf16 hi, row-major [p][128]
__device__ uint4 g_Al4[(size_t)MAXN * 16];   // bf16 lo
__device__ uint4 g_Bh4[K2 * 16];             // w2 hi, [n][128]
__device__ uint4 g_Bl4[K2 * 16];
__device__ float g_mom[1088];                // Sxx[32*32] + sums[32]
__device__ float g_bn1[2 * K1];
__device__ float g_s2[2 * K2];
__device__ float g_bn2[2 * K2];
__device__ float g_pooled[MAXB * K2 * CIN];
__device__ float g_resraw[MAXB * FCD];

__device__ __forceinline__ u64 pk2(float lo, float hi) {
    u64 r; asm("mov.b64 %0, {%1, %2};" : "=l"(r) : "f"(lo), "f"(hi)); return r;
}
__device__ __forceinline__ void fma2(u64 &d, u64 a, u64 b) {
    asm("fma.rn.f32x2 %0, %1, %2, %0;" : "+l"(d) : "l"(a), "l"(b));
}
__device__ __forceinline__ float2 upk2(u64 v) {
    float lo, hi; asm("mov.b64 {%0, %1}, %2;" : "=f"(lo), "=f"(hi) : "l"(v));
    return make_float2(lo, hi);
}
__device__ __forceinline__ uint32_t smem_u32(const void* p) {
    uint32_t a;
    asm("{ .reg .u64 t; cvta.to.shared.u64 t, %1; cvt.u32.u64 %0, t; }" : "=r"(a) : "l"(p));
    return a;
}
__device__ __forceinline__ void cpasync16(uint32_t dst, const void* src) {
    asm volatile("cp.async.cg.shared.global [%0], [%1], 16;" :: "r"(dst), "l"(src));
}
#define CP_COMMIT() asm volatile("cp.async.commit_group;" ::: "memory")

__device__ __forceinline__ void ldm4(uint32_t* r, uint32_t a) {
    asm volatile("ldmatrix.sync.aligned.m8n8.x4.shared.b16 {%0,%1,%2,%3}, [%4];"
        : "=r"(r[0]), "=r"(r[1]), "=r"(r[2]), "=r"(r[3]) : "r"(a));
}
__device__ __forceinline__ void mma16816(float* d, const uint32_t* a, uint32_t b0, uint32_t b1) {
    asm volatile("mma.sync.aligned.m16n8k16.row.col.f32.bf16.bf16.f32 "
        "{%0,%1,%2,%3}, {%4,%5,%6,%7}, {%8,%9}, {%0,%1,%2,%3};"
        : "+f"(d[0]), "+f"(d[1]), "+f"(d[2]), "+f"(d[3])
        : "r"(a[0]), "r"(a[1]), "r"(a[2]), "r"(a[3]), "r"(b0), "r"(b1));
}

__device__ __forceinline__ void split8(const float* v, uint32_t* hw, uint32_t* lw) {
#pragma unroll
    for (int j = 0; j < 4; j++) {
        float f0 = v[2 * j], f1 = v[2 * j + 1];
        __nv_bfloat162 h2 = __floats2bfloat162_rn(f0, f1);
        float r0 = f0 - __low2float(h2);
        float r1 = f1 - __high2float(h2);
        __nv_bfloat162 l2 = __floats2bfloat162_rn(r0, r1);
        memcpy(&hw[j], &h2, 4); memcpy(&lw[j], &l2, 4);
    }
}

__global__ void k_zero(float* outp, int B) {
    int i = blockIdx.x * blockDim.x + threadIdx.x;
    if (i < B * K2 * CIN) g_pooled[i] = 0.f;
    if (i < 1088) g_mom[i] = 0.f;
    if (i < 2 * K2) g_s2[i] = 0.f;
    if (i < B * K2) outp[B * FCD + i] = 0.f;
}

__global__ void k_prepb(const float* __restrict__ w2) {
    int i = blockIdx.x * 256 + threadIdx.x;
    if (i >= K2 * 16) return;
    int n = i >> 4, q = i & 15;
    float v[8];
    *(float4*)v       = *(const float4*)(w2 + (size_t)n * 128 + q * 8);
    *(float4*)(v + 4) = *(const float4*)(w2 + (size_t)n * 128 + q * 8 + 4);
    uint32_t hw[4], lw[4];
    split8(v, hw, lw);
    g_Bh4[n * 16 + q] = make_uint4(hw[0], hw[1], hw[2], hw[3]);
    g_Bl4[n * 16 + q] = make_uint4(lw[0], lw[1], lw[2], lw[3]);
}

// ---- x moments: Sxx = sum x x^T (32x32), sums = sum x ----
__global__ __launch_bounds__(256) void k_moments(const float* __restrict__ x, int N) {
    __shared__ float xs[128 * 34];
    int tid = threadIdx.x;
    int tt = tid & 31, rep = tid >> 5;           // 32 tiles x 8 reps
    int i0 = (tt >> 2) * 4, j0 = (tt & 3) * 8;
    int npb = N / gridDim.x;                     // points per block (8192)
    size_t base = (size_t)blockIdx.x * npb;
    u64 acc[4][4];
#pragma unroll
    for (int a = 0; a < 4; a++)
#pragma unroll
        for (int q = 0; q < 4; q++) acc[a][q] = 0ull;
    float ssum[4] = {0.f, 0.f, 0.f, 0.f};

    for (int t = 0; t < npb / 128; t++) {
        __syncthreads();
        for (int i = tid; i < 1024; i += 256) {
            int p = i >> 3, q = i & 7;
            float4 v = *(const float4*)&x[(base + t * 128 + p) * CIN + q * 4];
            *(float2*)&xs[p * 34 + q * 4]     = make_float2(v.x, v.y);
            *(float2*)&xs[p * 34 + q * 4 + 2] = make_float2(v.z, v.w);
        }
        __syncthreads();
        for (int pp = 0; pp < 16; pp++) {
            const float* xr = &xs[(rep * 16 + pp) * 34];
            float xi[4];
#pragma unroll
            for (int a = 0; a < 4; a++) xi[a] = xr[i0 + a];
            u64 xj[4];
#pragma unroll
            for (int q = 0; q < 4; q++) xj[q] = *(const u64*)&xr[j0 + 2 * q];
#pragma unroll
            for (int a = 0; a < 4; a++) {
                u64 ap = pk2(xi[a], xi[a]);
#pragma unroll
                for (int q = 0; q < 4; q++) fma2(acc[a][q], ap, xj[q]);
            }
            if ((tt & 3) == 0) {
#pragma unroll
                for (int a = 0; a < 4; a++) ssum[a] += xi[a];
            }
        }
    }
#pragma unroll
    for (int a = 0; a < 4; a++)
#pragma unroll
        for (int q = 0; q < 4; q++) {
            float2 f = upk2(acc[a][q]);
            atomicAdd(&g_mom[(i0 + a) * 32 + j0 + 2 * q], f.x);
            atomicAdd(&g_mom[(i0 + a) * 32 + j0 + 2 * q + 1], f.y);
        }
    if ((tt & 3) == 0)
#pragma unroll
        for (int a = 0; a < 4; a++) atomicAdd(&g_mom[1024 + i0 + a], ssum[a]);
}

// ---- BN1 coefs analytically from moments ----
__global__ void k_fin1(const float* __restrict__ w1, const float* __restrict__ b1,
                       const float* __restrict__ g1, const float* __restrict__ be1,
                       float invN) {
    int k = threadIdx.x;
    float wv[32];
#pragma unroll
    for (int i = 0; i < 32; i++) wv[i] = w1[k * 32 + i];
    float q2 = 0.f, mulin = 0.f;
    for (int i = 0; i < 32; i++) {
        float wi = wv[i];
        mulin += wi * g_mom[1024 + i];
        float t = 0.f;
        for (int j = 0; j < 32; j++) t += wv[j] * g_mom[i * 32 + j];
        q2 += wi * t;
    }
    mulin *= invN;
    float bk = b1[k];
    float mu = mulin + bk;
    float Eh2 = q2 * invN + 2.f * bk * mulin + bk * bk;
    float var = Eh2 - mu * mu;
    float a = g1[k] * rsqrtf(var + 1e-5f);
    g_bn1[k] = a;
    g_bn1[K1 + k] = fmaf(-mu, a, be1[k]);
}

// ---- fused GEMM1 + bn1 + relu + bf16 hi/lo split -> A images ----
__global__ __launch_bounds__(256) void k_gemm1f(const float* __restrict__ x,
                                                const float* __restrict__ w1,
                                                const float* __restrict__ b1, int N) {
    __shared__ __align__(16) float w1s[K1 * CIN];
    __shared__ float cf[3 * K1];                  // a1, c1, b1
    __shared__ uint32_t sh_hi[256 * 17];
    __shared__ uint32_t sh_lo[256 * 17];
    int tid = threadIdx.x;
    for (int i = tid; i < K1 * CIN; i += 256) w1s[i] = w1[i];
    if (tid < K1) {
        cf[tid] = g_bn1[tid];
        cf[K1 + tid] = g_bn1[K1 + tid];
        cf[2 * K1 + tid] = b1[tid];
    }
    size_t p0 = (size_t)blockIdx.x * 256;
    size_t p = p0 + tid;
    u64 xp2[16];
    const float4* xp = (const float4*)(x + p * CIN);
#pragma unroll
    for (int q = 0; q < 8; q++) {
        float4 v = xp[q];
        xp2[2 * q] = pk2(v.x, v.y); xp2[2 * q + 1] = pk2(v.z, v.w);
    }
    __syncthreads();
    for (int cc = 0; cc < 4; cc++) {
#pragma unroll 2
        for (int chp = 0; chp < 16; chp++) {
            int ch0 = cc * 32 + chp * 2;
            float an[2];
#pragma unroll
            for (int s = 0; s < 2; s++) {
                int ch = ch0 + s;
                const u64* wr = (const u64*)(w1s + ch * CIN);
                u64 a = 0ull;
#pragma unroll
                for (int q = 0; q < 16; q++) fma2(a, xp2[q], wr[q]);
                float2 f = upk2(a);
                float h = f.x + f.y + cf[2 * K1 + ch];
                an[s] = fmaxf(fmaf(cf[ch], h, cf[K1 + ch]), 0.f);
            }
            __nv_bfloat162 h2 = __floats2bfloat162_rn(an[0], an[1]);
            float r0 = an[0] - __low2float(h2);
            float r1 = an[1] - __high2float(h2);
            __nv_bfloat162 l2 = __floats2bfloat162_rn(r0, r1);
            uint32_t hu, lu; memcpy(&hu, &h2, 4); memcpy(&lu, &l2, 4);
            sh_hi[tid * 17 + chp] = hu;
            sh_lo[tid * 17 + chp] = lu;
        }
        __syncthreads();
        for (int i = tid; i < 1024; i += 256) {
            int pp = i >> 2, q4 = i & 3;
            uint4 vh, vl;
            vh.x = sh_hi[pp * 17 + q4 * 4];     vh.y = sh_hi[pp * 17 + q4 * 4 + 1];
            vh.z = sh_hi[pp * 17 + q4 * 4 + 2]; vh.w = sh_hi[pp * 17 + q4 * 4 + 3];
            vl.x = sh_lo[pp * 17 + q4 * 4];     vl.y = sh_lo[pp * 17 + q4 * 4 + 1];
            vl.z = sh_lo[pp * 17 + q4 * 4 + 2]; vl.w = sh_lo[pp * 17 + q4 * 4 + 3];
            g_Ah4[(p0 + pp) * 16 + cc * 4 + q4] = vh;
            g_Al4[(p0 + pp) * 16 + cc * 4 + q4] = vl;
        }
        __syncthreads();
    }
}

// ---- GEMM2 via HMMA bf16x3: att = A·B^T + b2, fused BN2 stats ----
#define STG_SZ 40960
#define SM_TOTAL 82432

__global__ __launch_bounds__(256, 2) void k_gemm2_mma(const float* __restrict__ b2, int N) {
    extern __shared__ char smem[];
    uint32_t sb = smem_u32(smem);
    int tid = threadIdx.x, lane = tid & 31, wid = tid >> 5;
    int wm = wid >> 1, wn = wid & 1;
    int nb = blockIdx.x;
    int n0 = nb * 128;
    size_t p0 = (size_t)blockIdx.y * 128;
    float* bs = (float*)(smem + 81920);
    if (tid < 128) bs[tid] = b2[n0 + tid];

    auto copy_chunk = [&](int ck, uint32_t stg) {
        for (int e = tid; e < 2048; e += 256) {
            int part = e >> 10, sub = (e >> 9) & 1;
            int r = (e & 511) >> 2, cc = e & 3;
            uint32_t dst = stg + (uint32_t)((part * 2 + sub) * 10240 + r * 80 + cc * 16);
            const char* base = part ? (sub ? (const char*)g_Bl4 : (const char*)g_Bh4)
                                    : (sub ? (const char*)g_Al4 : (const char*)g_Ah4);
            size_t row = part ? (size_t)(n0 + r) : (p0 + r);
            cpasync16(dst, base + row * 256 + ck * 64 + cc * 16);
        }
        CP_COMMIT();
    };
    copy_chunk(0, sb);
    copy_chunk(1, sb + STG_SZ);

    float acc[2][8][4];
#pragma unroll
    for (int mi = 0; mi < 2; mi++)
#pragma unroll
        for (int c = 0; c < 8; c++)
#pragma unroll
            for (int j = 0; j < 4; j++) acc[mi][c][j] = 0.f;

    uint32_t laneOff = (uint32_t)((lane & 15) * 80 + (lane >> 4) * 16);

    for (int c = 0; c < 4; c++) {
        if (c < 3) asm volatile("cp.async.wait_group 1;" ::: "memory");
        else       asm volatile("cp.async.wait_group 0;" ::: "memory");
        __syncthreads();
        uint32_t stg = sb + (uint32_t)(c & 1) * STG_SZ;
        uint32_t aBase = stg + (uint32_t)(wm * 32 * 80) + laneOff;
        uint32_t bBase = stg + 20480u + (uint32_t)(wn * 64 * 80) + laneOff;
#pragma unroll
        for (int ksl = 0; ksl < 2; ksl++) {
            uint32_t ah[2][4], al[2][4];
#pragma unroll
            for (int mi = 0; mi < 2; mi++) {
                ldm4(ah[mi], aBase + mi * 1280 + ksl * 32);
                ldm4(al[mi], aBase + 10240 + mi * 1280 + ksl * 32);
            }
#pragma unroll
            for (int nj = 0; nj < 4; nj++) {
                uint32_t bh[4], bl[4];
                ldm4(bh, bBase + nj * 1280 + ksl * 32);
                ldm4(bl, bBase + 10240 + nj * 1280 + ksl * 32);
#pragma unroll
                for (int mi = 0; mi < 2; mi++)
#pragma unroll
                    for (int s = 0; s < 2; s++) {
                        float* d = acc[mi][nj * 2 + s];
                        mma16816(d, ah[mi], bh[s], bh[s + 2]);
                        mma16816(d, ah[mi], bl[s], bl[s + 2]);
                        mma16816(d, al[mi], bh[s], bh[s + 2]);
                    }
            }
        }
        __syncthreads();
        if (c < 2) copy_chunk(c + 2, sb + (uint32_t)(c & 1) * STG_SZ);
    }

    float* stgf = (float*)smem;
    int t4 = lane >> 2, t2 = 2 * (lane & 3);
#pragma unroll
    for (int mi = 0; mi < 2; mi++) {
        int mB = wm * 32 + mi * 16 + t4;
#pragma unroll
        for (int c = 0; c < 8; c++) {
            int nn = wn * 64 + c * 8 + t2;
            float* d = acc[mi][c];
            *(float2*)&stgf[mB * 128 + (nn ^ ((mB & 7) << 2))] = make_float2(d[0], d[1]);
            int m2 = mB + 8;
            *(float2*)&stgf[m2 * 128 + (nn ^ ((m2 & 7) << 2))] = make_float2(d[2], d[3]);
        }
    }
    __syncthreads();
#pragma unroll
    for (int it = 0; it < 16; it++) {
        int task = tid + it * 256;
        int rr = task >> 5, c4 = (task & 31) * 4;
        float4 v = *(const float4*)&stgf[rr * 128 + (c4 ^ ((rr & 7) << 2))];
        float4 bb = *(const float4*)&bs[c4];
        v.x += bb.x; v.y += bb.y; v.z += bb.z; v.w += bb.w;
        *(float4*)&g_att[(p0 + rr) * K2 + n0 + c4] = v;
    }
    {
        int col = tid & 127, half = tid >> 7;
        float bias = bs[col];
        float s = 0.f, q = 0.f;
        for (int r = half * 64; r < half * 64 + 64; r++) {
            float v = stgf[r * 128 + (col ^ ((r & 7) << 2))] + bias;
            s += v; q += v * v;
        }
        atomicAdd(&g_s2[n0 + col], s);
        atomicAdd(&g_s2[K2 + n0 + col], q);
    }
}

__global__ void k_fin2(const float* __restrict__ g2, const float* __restrict__ be2, float invN) {
    int k = threadIdx.x;
    float mu = g_s2[k] * invN;
    float var = g_s2[K2 + k] * invN - mu * mu;
    float a = g2[k] * rsqrtf(var + 1e-5f);
    g_bn2[k] = a;
    g_bn2[K2 + k] = fmaf(-mu, a, be2[k]);
}

// ---- pooling: register-blocked 4k x 8c, 4-way l-split ----
__global__ __launch_bounds__(256) void k_pool(const float* __restrict__ x,
                                              float* __restrict__ gp_out, int L) {
    __shared__ float Att[32][64];
    __shared__ __align__(16) float Xs[32][32];
    __shared__ float bn2s[2][64];
    __shared__ float psum[64][33];
    __shared__ float gps[64];
    int b = blockIdx.x;
    int k0 = blockIdx.y * 64;
    int lsl = L >> 3;
    size_t pbase = (size_t)b * L + (size_t)blockIdx.z * lsl;
    int tid = threadIdx.x;
    if (tid < 64) {
        bn2s[0][tid] = g_bn2[k0 + tid];
        bn2s[1][tid] = g_bn2[K2 + k0 + tid];
        gps[tid] = 0.f;
    }
    for (int i = tid; i < 64 * 33; i += 256) (&psum[0][0])[i] = 0.f;
    int kq = (tid & 63) >> 2, cg = tid & 3, rep = tid >> 6;
    u64 acc[4][4];
#pragma unroll
    for (int a = 0; a < 4; a++)
#pragma unroll
        for (int q = 0; q < 4; q++) acc[a][q] = 0ull;
    float gpl[4] = {0.f, 0.f, 0.f, 0.f};

    for (int lc = 0; lc < lsl; lc += 32) {
        __syncthreads();
        for (int i = tid; i < 32 * 16; i += 256) {
            int r = i >> 4, c4 = (i & 15) * 4;
            float4 v = *(const float4*)&g_att[(pbase + lc + r) * K2 + k0 + c4];
            Att[r][c4]     = fmaxf(fmaf(bn2s[0][c4],     v.x, bn2s[1][c4]),     0.f);
            Att[r][c4 + 1] = fmaxf(fmaf(bn2s[0][c4 + 1], v.y, bn2s[1][c4 + 1]), 0.f);
            Att[r][c4 + 2] = fmaxf(fmaf(bn2s[0][c4 + 2], v.z, bn2s[1][c4 + 2]), 0.f);
            Att[r][c4 + 3] = fmaxf(fmaf(bn2s[0][c4 + 3], v.w, bn2s[1][c4 + 3]), 0.f);
        }
        for (int i = tid; i < 32 * 8; i += 256) {
            int r = i >> 3, c4 = (i & 7) * 4;
            *(float4*)&Xs[r][c4] = *(const float4*)&x[(pbase + lc + r) * CIN + c4];
        }
        __syncthreads();
#pragma unroll 2
        for (int l = rep * 8; l < rep * 8 + 8; l++) {
            float av[4];
#pragma unroll
            for (int a = 0; a < 4; a++) av[a] = Att[l][kq * 4 + a];
            if (cg == 0) {
#pragma unroll
                for (int a = 0; a < 4; a++) gpl[a] += av[a];
            }
            u64 xj[4];
#pragma unroll
            for (int q = 0; q < 4; q++) xj[q] = *(const u64*)&Xs[l][cg * 8 + 2 * q];
#pragma unroll
            for (int a = 0; a < 4; a++) {
                u64 ap = pk2(av[a], av[a]);
#pragma unroll
                for (int q = 0; q < 4; q++) fma2(acc[a][q], ap, xj[q]);
            }
        }
    }
    __syncthreads();
#pragma unroll
    for (int a = 0; a < 4; a++)
#pragma unroll
        for (int q = 0; q < 4; q++) {
            float2 f = upk2(acc[a][q]);
            atomicAdd(&psum[kq * 4 + a][cg * 8 + 2 * q], f.x);
            atomicAdd(&psum[kq * 4 + a][cg * 8 + 2 * q + 1], f.y);
        }
    if (cg == 0)
#pragma unroll
        for (int a = 0; a < 4; a++) atomicAdd(&gps[kq * 4 + a], gpl[a]);
    __syncthreads();
    for (int i = tid; i < 2048; i += 256) {
        int kk = i >> 5, c = i & 31;
        atomicAdd(&g_pooled[((size_t)b * K2 + k0 + kk) * CIN + c], psum[kk][c]);
    }
    if (tid < 64) atomicAdd(&gp_out[b * K2 + k0 + tid], gps[tid]);
}

__global__ __launch_bounds__(256) void k_fc(const float* __restrict__ wf,
                                            const float* __restrict__ bf,
                                            int B, float invL) {
    int j = blockIdx.x, tid = threadIdx.x;
    const float* wrow = wf + (size_t)j * (K2 * CIN);
    float acc[MAXB];
#pragma unroll
    for (int b = 0; b < MAXB; b++) acc[b] = 0.f;
    for (int i = tid; i < K2 * CIN; i += 256) {
        float w = wrow[i];
#pragma unroll
        for (int b = 0; b < MAXB; b++)
            if (b < B) acc[b] += w * g_pooled[(size_t)b * (K2 * CIN) + i];
    }
    __shared__ float red[8][MAXB];
    int lane = tid & 31, w = tid >> 5;
#pragma unroll
    for (int b = 0; b < MAXB; b++) {
        float v = acc[b];
#pragma unroll
        for (int o = 16; o; o >>= 1) v += __shfl_down_sync(0xffffffffu, v, o);
        if (lane == 0) red[w][b] = v;
    }
    __syncthreads();
    if (tid < B) {
        float ssum = 0.f;
        for (int i = 0; i < 8; i++) ssum += red[i][tid];
        g_resraw[tid * FCD + j] = fmaf(ssum, invL, bf[j]);
    }
}

__global__ void k_final(float* __restrict__ outp, const float* __restrict__ gf,
                        const float* __restrict__ bef, int B, int L) {
    int j = threadIdx.x;
    __shared__ float rows[MAXB];
    if (j < B) rows[j] = 0.f;
    __syncthreads();
    float v[MAXB];
    float s = 0.f, q = 0.f;
    for (int b = 0; b < B; b++) {
        v[b] = g_resraw[b * FCD + j];
        s += v[b]; q += v[b] * v[b];
    }
    float invB = 1.f / (float)B;
    float mu = s * invB;
    float var = q * invB - mu * mu;
    float a = gf[j] * rsqrtf(var + 1e-5f);
    float c = fmaf(-mu, a, bef[j]);
    for (int b = 0; b < B; b++) {
        v[b] = fmaf(a, v[b], c);
        atomicAdd(&rows[b], v[b] * v[b]);
    }
    __syncthreads();
    for (int b = 0; b < B; b++)
        outp[b * FCD + j] = v[b] / fmaxf(sqrtf(rows[b]), 1e-12f);
    if (j < B) outp[B * FCD + B * K2 + j] = (float)L;
}

extern "C" void kernel_launch(void* const* d_in, const int* in_sizes, int n_in,
                              void* d_out, int out_size) {
    const float* x   = (const float*)d_in[0];
    const float* w1  = (const float*)d_in[1];
    const float* b1  = (const float*)d_in[2];
    const float* g1  = (const float*)d_in[3];
    const float* be1 = (const float*)d_in[4];
    const float* w2  = (const float*)d_in[5];
    const float* b2  = (const float*)d_in[6];
    const float* g2  = (const float*)d_in[7];
    const float* be2 = (const float*)d_in[8];
    const float* wf  = (const float*)d_in[9];
    const float* bf  = (const float*)d_in[10];
    const float* gf  = (const float*)d_in[11];
    const float* bef = (const float*)d_in[12];
    float* outp = (float*)d_out;

    int N = in_sizes[0] / CIN;
    int B = out_size / (FCD + K2 + 1);
    int L = N / B;
    float invN = 1.f / (float)N;
    float invL = 1.f / (float)L;

    cudaFuncSetAttribute(k_gemm2_mma, cudaFuncAttributeMaxDynamicSharedMemorySize, SM_TOTAL);

    k_zero<<<(B * K2 * CIN + 255) / 256, 256>>>(outp, B);
    k_prepb<<<(K2 * 16 + 255) / 256, 256>>>(w2);
    k_moments<<<N / 8192, 256>>>(x, N);
    k_fin1<<<1, K1>>>(w1, b1, g1, be1, invN);
    k_gemm1f<<<N / 256, 256>>>(x, w1, b1, N);
    k_gemm2_mma<<<dim3(4, N / 128), 256, SM_TOTAL>>>(b2, N);
    k_fin2<<<1, K2>>>(g2, be2, invN);
    k_pool<<<dim3(B, K2 / 64, 8), 256>>>(x, outp + B * FCD, L);
    k_fc<<<FCD, 256>>>(wf, bf, B, invL);
    k_final<<<1, FCD>>>(outp, gf, bef, B, L);
}

// round 9
// speedup vs baseline: 1.8768x; 1.0020x over previous
#include <cuda_runtime.h>
#include <cuda_bf16.h>
#include <cstdint>
#include <cstddef>
#include <cstring>

#define CIN 32
#define K1  128
#define K2  512
#define FCD 256
#define MAXN 524288
#define MAXB 16

typedef unsigned long long u64;

__device__ float g_att[(size_t)MAXN * K2];
__device__ uint4 g_Ah4[(size_t)MAXN * 16];   // bf16 hi, row-major [p][128]
__device__ uint4 g_Al4[(size_t)MAXN * 16];   // bf16 lo
__device__ uint4 g_Bh4[K2 * 16];             // w2 hi, [n][128]
__device__ uint4 g_Bl4[K2 * 16];
__device__ float g_mom[1088];                // Sxx[32*32] + sums[32]
__device__ float g_bn1[2 * K1];
__device__ float g_s2[2 * K2];
__device__ float g_bn2[2 * K2];
__device__ float g_pooled[MAXB * K2 * CIN];
__device__ float g_resraw[MAXB * FCD];

__device__ __forceinline__ u64 pk2(float lo, float hi) {
    u64 r; asm("mov.b64 %0, {%1, %2};" : "=l"(r) : "f"(lo), "f"(hi)); return r;
}
__device__ __forceinline__ void fma2(u64 &d, u64 a, u64 b) {
    asm("fma.rn.f32x2 %0, %1, %2, %0;" : "+l"(d) : "l"(a), "l"(b));
}
__device__ __forceinline__ float2 upk2(u64 v) {
    float lo, hi; asm("mov.b64 {%0, %1}, %2;" : "=f"(lo), "=f"(hi) : "l"(v));
    return make_float2(lo, hi);
}
__device__ __forceinline__ uint32_t smem_u32(const void* p) {
    uint32_t a;
    asm("{ .reg .u64 t; cvta.to.shared.u64 t, %1; cvt.u32.u64 %0, t; }" : "=r"(a) : "l"(p));
    return a;
}
__device__ __forceinline__ void cpasync16(uint32_t dst, const void* src) {
    asm volatile("cp.async.cg.shared.global [%0], [%1], 16;" :: "r"(dst), "l"(src));
}
#define CP_COMMIT() asm volatile("cp.async.commit_group;" ::: "memory")

__device__ __forceinline__ void ldm4(uint32_t* r, uint32_t a) {
    asm volatile("ldmatrix.sync.aligned.m8n8.x4.shared.b16 {%0,%1,%2,%3}, [%4];"
        : "=r"(r[0]), "=r"(r[1]), "=r"(r[2]), "=r"(r[3]) : "r"(a));
}
__device__ __forceinline__ void mma16816(float* d, const uint32_t* a, uint32_t b0, uint32_t b1) {
    asm volatile("mma.sync.aligned.m16n8k16.row.col.f32.bf16.bf16.f32 "
        "{%0,%1,%2,%3}, {%4,%5,%6,%7}, {%8,%9}, {%0,%1,%2,%3};"
        : "+f"(d[0]), "+f"(d[1]), "+f"(d[2]), "+f"(d[3])
        : "r"(a[0]), "r"(a[1]), "r"(a[2]), "r"(a[3]), "r"(b0), "r"(b1));
}

__device__ __forceinline__ void split8(const float* v, uint32_t* hw, uint32_t* lw) {
#pragma unroll
    for (int j = 0; j < 4; j++) {
        float f0 = v[2 * j], f1 = v[2 * j + 1];
        __nv_bfloat162 h2 = __floats2bfloat162_rn(f0, f1);
        float r0 = f0 - __low2float(h2);
        float r1 = f1 - __high2float(h2);
        __nv_bfloat162 l2 = __floats2bfloat162_rn(r0, r1);
        memcpy(&hw[j], &h2, 4); memcpy(&lw[j], &l2, 4);
    }
}

__global__ void k_zero(float* outp, int B) {
    int i = blockIdx.x * blockDim.x + threadIdx.x;
    if (i < B * K2 * CIN) g_pooled[i] = 0.f;
    if (i < 1088) g_mom[i] = 0.f;
    if (i < 2 * K2) g_s2[i] = 0.f;
    if (i < B * K2) outp[B * FCD + i] = 0.f;
}

__global__ void k_prepb(const float* __restrict__ w2) {
    int i = blockIdx.x * 256 + threadIdx.x;
    if (i >= K2 * 16) return;
    int n = i >> 4, q = i & 15;
    float v[8];
    *(float4*)v       = *(const float4*)(w2 + (size_t)n * 128 + q * 8);
    *(float4*)(v + 4) = *(const float4*)(w2 + (size_t)n * 128 + q * 8 + 4);
    uint32_t hw[4], lw[4];
    split8(v, hw, lw);
    g_Bh4[n * 16 + q] = make_uint4(hw[0], hw[1], hw[2], hw[3]);
    g_Bl4[n * 16 + q] = make_uint4(lw[0], lw[1], lw[2], lw[3]);
}

// ---- x moments: Sxx = sum x x^T (32x32), sums = sum x ----
__global__ __launch_bounds__(256) void k_moments(const float* __restrict__ x, int N) {
    __shared__ float xs[128 * 34];
    int tid = threadIdx.x;
    int tt = tid & 31, rep = tid >> 5;           // 32 tiles x 8 reps
    int i0 = (tt >> 2) * 4, j0 = (tt & 3) * 8;
    int npb = N / gridDim.x;                     // points per block (8192)
    size_t base = (size_t)blockIdx.x * npb;
    u64 acc[4][4];
#pragma unroll
    for (int a = 0; a < 4; a++)
#pragma unroll
        for (int q = 0; q < 4; q++) acc[a][q] = 0ull;
    float ssum[4] = {0.f, 0.f, 0.f, 0.f};

    for (int t = 0; t < npb / 128; t++) {
        __syncthreads();
        for (int i = tid; i < 1024; i += 256) {
            int p = i >> 3, q = i & 7;
            float4 v = *(const float4*)&x[(base + t * 128 + p) * CIN + q * 4];
            *(float2*)&xs[p * 34 + q * 4]     = make_float2(v.x, v.y);
            *(float2*)&xs[p * 34 + q * 4 + 2] = make_float2(v.z, v.w);
        }
        __syncthreads();
        for (int pp = 0; pp < 16; pp++) {
            const float* xr = &xs[(rep * 16 + pp) * 34];
            float xi[4];
#pragma unroll
            for (int a = 0; a < 4; a++) xi[a] = xr[i0 + a];
            u64 xj[4];
#pragma unroll
            for (int q = 0; q < 4; q++) xj[q] = *(const u64*)&xr[j0 + 2 * q];
#pragma unroll
            for (int a = 0; a < 4; a++) {
                u64 ap = pk2(xi[a], xi[a]);
#pragma unroll
                for (int q = 0; q < 4; q++) fma2(acc[a][q], ap, xj[q]);
            }
            if ((tt & 3) == 0) {
#pragma unroll
                for (int a = 0; a < 4; a++) ssum[a] += xi[a];
            }
        }
    }
#pragma unroll
    for (int a = 0; a < 4; a++)
#pragma unroll
        for (int q = 0; q < 4; q++) {
            float2 f = upk2(acc[a][q]);
            atomicAdd(&g_mom[(i0 + a) * 32 + j0 + 2 * q], f.x);
            atomicAdd(&g_mom[(i0 + a) * 32 + j0 + 2 * q + 1], f.y);
        }
    if ((tt & 3) == 0)
#pragma unroll
        for (int a = 0; a < 4; a++) atomicAdd(&g_mom[1024 + i0 + a], ssum[a]);
}

// ---- BN1 coefs analytically from moments ----
__global__ void k_fin1(const float* __restrict__ w1, const float* __restrict__ b1,
                       const float* __restrict__ g1, const float* __restrict__ be1,
                       float invN) {
    int k = threadIdx.x;
    float wv[32];
#pragma unroll
    for (int i = 0; i < 32; i++) wv[i] = w1[k * 32 + i];
    float q2 = 0.f, mulin = 0.f;
    for (int i = 0; i < 32; i++) {
        float wi = wv[i];
        mulin += wi * g_mom[1024 + i];
        float t = 0.f;
        for (int j = 0; j < 32; j++) t += wv[j] * g_mom[i * 32 + j];
        q2 += wi * t;
    }
    mulin *= invN;
    float bk = b1[k];
    float mu = mulin + bk;
    float Eh2 = q2 * invN + 2.f * bk * mulin + bk * bk;
    float var = Eh2 - mu * mu;
    float a = g1[k] * rsqrtf(var + 1e-5f);
    g_bn1[k] = a;
    g_bn1[K1 + k] = fmaf(-mu, a, be1[k]);
}

// ---- fused GEMM1 + bn1 + relu + bf16 hi/lo split -> A images ----
__global__ __launch_bounds__(256) void k_gemm1f(const float* __restrict__ x,
                                                const float* __restrict__ w1,
                                                const float* __restrict__ b1, int N) {
    __shared__ __align__(16) float w1s[K1 * CIN];
    __shared__ float cf[3 * K1];                  // a1, c1, b1
    __shared__ uint32_t sh_hi[256 * 17];
    __shared__ uint32_t sh_lo[256 * 17];
    int tid = threadIdx.x;
    for (int i = tid; i < K1 * CIN; i += 256) w1s[i] = w1[i];
    if (tid < K1) {
        cf[tid] = g_bn1[tid];
        cf[K1 + tid] = g_bn1[K1 + tid];
        cf[2 * K1 + tid] = b1[tid];
    }
    size_t p0 = (size_t)blockIdx.x * 256;
    size_t p = p0 + tid;
    u64 xp2[16];
    const float4* xp = (const float4*)(x + p * CIN);
#pragma unroll
    for (int q = 0; q < 8; q++) {
        float4 v = xp[q];
        xp2[2 * q] = pk2(v.x, v.y); xp2[2 * q + 1] = pk2(v.z, v.w);
    }
    __syncthreads();
    for (int cc = 0; cc < 4; cc++) {
#pragma unroll 2
        for (int chp = 0; chp < 16; chp++) {
            int ch0 = cc * 32 + chp * 2;
            float an[2];
#pragma unroll
            for (int s = 0; s < 2; s++) {
                int ch = ch0 + s;
                const u64* wr = (const u64*)(w1s + ch * CIN);
                u64 a = 0ull;
#pragma unroll
                for (int q = 0; q < 16; q++) fma2(a, xp2[q], wr[q]);
                float2 f = upk2(a);
                float h = f.x + f.y + cf[2 * K1 + ch];
                an[s] = fmaxf(fmaf(cf[ch], h, cf[K1 + ch]), 0.f);
            }
            __nv_bfloat162 h2 = __floats2bfloat162_rn(an[0], an[1]);
            float r0 = an[0] - __low2float(h2);
            float r1 = an[1] - __high2float(h2);
            __nv_bfloat162 l2 = __floats2bfloat162_rn(r0, r1);
            uint32_t hu, lu; memcpy(&hu, &h2, 4); memcpy(&lu, &l2, 4);
            sh_hi[tid * 17 + chp] = hu;
            sh_lo[tid * 17 + chp] = lu;
        }
        __syncthreads();
        for (int i = tid; i < 1024; i += 256) {
            int pp = i >> 2, q4 = i & 3;
            uint4 vh, vl;
            vh.x = sh_hi[pp * 17 + q4 * 4];     vh.y = sh_hi[pp * 17 + q4 * 4 + 1];
            vh.z = sh_hi[pp * 17 + q4 * 4 + 2]; vh.w = sh_hi[pp * 17 + q4 * 4 + 3];
            vl.x = sh_lo[pp * 17 + q4 * 4];     vl.y = sh_lo[pp * 17 + q4 * 4 + 1];
            vl.z = sh_lo[pp * 17 + q4 * 4 + 2]; vl.w = sh_lo[pp * 17 + q4 * 4 + 3];
            g_Ah4[(p0 + pp) * 16 + cc * 4 + q4] = vh;
            g_Al4[(p0 + pp) * 16 + cc * 4 + q4] = vl;
        }
        __syncthreads();
    }
}

// ---- GEMM2 via HMMA bf16x3: att = A·B^T + b2, fused BN2 stats ----
#define STG_SZ 40960
#define SM_TOTAL 82432

__global__ __launch_bounds__(256, 2) void k_gemm2_mma(const float* __restrict__ b2, int N) {
    extern __shared__ char smem[];
    uint32_t sb = smem_u32(smem);
    int tid = threadIdx.x, lane = tid & 31, wid = tid >> 5;
    int wm = wid >> 1, wn = wid & 1;
    int nb = blockIdx.x;
    int n0 = nb * 128;
    size_t p0 = (size_t)blockIdx.y * 128;
    float* bs = (float*)(smem + 81920);
    if (tid < 128) bs[tid] = b2[n0 + tid];

    auto copy_chunk = [&](int ck, uint32_t stg) {
        for (int e = tid; e < 2048; e += 256) {
            int part = e >> 10, sub = (e >> 9) & 1;
            int r = (e & 511) >> 2, cc = e & 3;
            uint32_t dst = stg + (uint32_t)((part * 2 + sub) * 10240 + r * 80 + cc * 16);
            const char* base = part ? (sub ? (const char*)g_Bl4 : (const char*)g_Bh4)
                                    : (sub ? (const char*)g_Al4 : (const char*)g_Ah4);
            size_t row = part ? (size_t)(n0 + r) : (p0 + r);
            cpasync16(dst, base + row * 256 + ck * 64 + cc * 16);
        }
        CP_COMMIT();
    };
    copy_chunk(0, sb);
    copy_chunk(1, sb + STG_SZ);

    float acc[2][8][4];
#pragma unroll
    for (int mi = 0; mi < 2; mi++)
#pragma unroll
        for (int c = 0; c < 8; c++)
#pragma unroll
            for (int j = 0; j < 4; j++) acc[mi][c][j] = 0.f;

    uint32_t laneOff = (uint32_t)((lane & 15) * 80 + (lane >> 4) * 16);

    for (int c = 0; c < 4; c++) {
        if (c < 3) asm volatile("cp.async.wait_group 1;" ::: "memory");
        else       asm volatile("cp.async.wait_group 0;" ::: "memory");
        __syncthreads();
        uint32_t stg = sb + (uint32_t)(c & 1) * STG_SZ;
        uint32_t aBase = stg + (uint32_t)(wm * 32 * 80) + laneOff;
        uint32_t bBase = stg + 20480u + (uint32_t)(wn * 64 * 80) + laneOff;
#pragma unroll
        for (int ksl = 0; ksl < 2; ksl++) {
            uint32_t ah[2][4], al[2][4];
#pragma unroll
            for (int mi = 0; mi < 2; mi++) {
                ldm4(ah[mi], aBase + mi * 1280 + ksl * 32);
                ldm4(al[mi], aBase + 10240 + mi * 1280 + ksl * 32);
            }
#pragma unroll
            for (int nj = 0; nj < 4; nj++) {
                uint32_t bh[4], bl[4];
                ldm4(bh, bBase + nj * 1280 + ksl * 32);
                ldm4(bl, bBase + 10240 + nj * 1280 + ksl * 32);
#pragma unroll
                for (int mi = 0; mi < 2; mi++)
#pragma unroll
                    for (int s = 0; s < 2; s++) {
                        float* d = acc[mi][nj * 2 + s];
                        mma16816(d, ah[mi], bh[s], bh[s + 2]);
                        mma16816(d, ah[mi], bl[s], bl[s + 2]);
                        mma16816(d, al[mi], bh[s], bh[s + 2]);
                    }
            }
        }
        __syncthreads();
        if (c < 2) copy_chunk(c + 2, sb + (uint32_t)(c & 1) * STG_SZ);
    }

    float* stgf = (float*)smem;
    int t4 = lane >> 2, t2 = 2 * (lane & 3);
#pragma unroll
    for (int mi = 0; mi < 2; mi++) {
        int mB = wm * 32 + mi * 16 + t4;
#pragma unroll
        for (int c = 0; c < 8; c++) {
            int nn = wn * 64 + c * 8 + t2;
            float* d = acc[mi][c];
            *(float2*)&stgf[mB * 128 + (nn ^ ((mB & 7) << 2))] = make_float2(d[0], d[1]);
            int m2 = mB + 8;
            *(float2*)&stgf[m2 * 128 + (nn ^ ((m2 & 7) << 2))] = make_float2(d[2], d[3]);
        }
    }
    __syncthreads();
#pragma unroll
    for (int it = 0; it < 16; it++) {
        int task = tid + it * 256;
        int rr = task >> 5, c4 = (task & 31) * 4;
        float4 v = *(const float4*)&stgf[rr * 128 + (c4 ^ ((rr & 7) << 2))];
        float4 bb = *(const float4*)&bs[c4];
        v.x += bb.x; v.y += bb.y; v.z += bb.z; v.w += bb.w;
        *(float4*)&g_att[(p0 + rr) * K2 + n0 + c4] = v;
    }
    {
        int col = tid & 127, half = tid >> 7;
        float bias = bs[col];
        float s = 0.f, q = 0.f;
        for (int r = half * 64; r < half * 64 + 64; r++) {
            float v = stgf[r * 128 + (col ^ ((r & 7) << 2))] + bias;
            s += v; q += v * v;
        }
        atomicAdd(&g_s2[n0 + col], s);
        atomicAdd(&g_s2[K2 + n0 + col], q);
    }
}

__global__ void k_fin2(const float* __restrict__ g2, const float* __restrict__ be2, float invN) {
    int k = threadIdx.x;
    float mu = g_s2[k] * invN;
    float var = g_s2[K2 + k] * invN - mu * mu;
    float a = g2[k] * rsqrtf(var + 1e-5f);
    g_bn2[k] = a;
    g_bn2[K2 + k] = fmaf(-mu, a, be2[k]);
}

// ---- pooling: register-blocked 4k x 8c, 4-way l-split ----
__global__ __launch_bounds__(256) void k_pool(const float* __restrict__ x,
                                              float* __restrict__ gp_out, int L) {
    __shared__ float Att[32][64];
    __shared__ __align__(16) float Xs[32][32];
    __shared__ float bn2s[2][64];
    __shared__ float psum[64][33];
    __shared__ float gps[64];
    int b = blockIdx.x;
    int k0 = blockIdx.y * 64;
    int lsl = L >> 3;
    size_t pbase = (size_t)b * L + (size_t)blockIdx.z * lsl;
    int tid = threadIdx.x;
    if (tid < 64) {
        bn2s[0][tid] = g_bn2[k0 + tid];
        bn2s[1][tid] = g_bn2[K2 + k0 + tid];
        gps[tid] = 0.f;
    }
    for (int i = tid; i < 64 * 33; i += 256) (&psum[0][0])[i] = 0.f;
    int kq = (tid & 63) >> 2, cg = tid & 3, rep = tid >> 6;
    u64 acc[4][4];
#pragma unroll
    for (int a = 0; a < 4; a++)
#pragma unroll
        for (int q = 0; q < 4; q++) acc[a][q] = 0ull;
    float gpl[4] = {0.f, 0.f, 0.f, 0.f};

    for (int lc = 0; lc < lsl; lc += 32) {
        __syncthreads();
        for (int i = tid; i < 32 * 16; i += 256) {
            int r = i >> 4, c4 = (i & 15) * 4;
            float4 v = *(const float4*)&g_att[(pbase + lc + r) * K2 + k0 + c4];
            Att[r][c4]     = fmaxf(fmaf(bn2s[0][c4],     v.x, bn2s[1][c4]),     0.f);
            Att[r][c4 + 1] = fmaxf(fmaf(bn2s[0][c4 + 1], v.y, bn2s[1][c4 + 1]), 0.f);
            Att[r][c4 + 2] = fmaxf(fmaf(bn2s[0][c4 + 2], v.z, bn2s[1][c4 + 2]), 0.f);
            Att[r][c4 + 3] = fmaxf(fmaf(bn2s[0][c4 + 3], v.w, bn2s[1][c4 + 3]), 0.f);
        }
        for (int i = tid; i < 32 * 8; i += 256) {
            int r = i >> 3, c4 = (i & 7) * 4;
            *(float4*)&Xs[r][c4] = *(const float4*)&x[(pbase + lc + r) * CIN + c4];
        }
        __syncthreads();
#pragma unroll 2
        for (int l = rep * 8; l < rep * 8 + 8; l++) {
            float av[4];
#pragma unroll
            for (int a = 0; a < 4; a++) av[a] = Att[l][kq * 4 + a];
            if (cg == 0) {
#pragma unroll
                for (int a = 0; a < 4; a++) gpl[a] += av[a];
            }
            u64 xj[4];
#pragma unroll
            for (int q = 0; q < 4; q++) xj[q] = *(const u64*)&Xs[l][cg * 8 + 2 * q];
#pragma unroll
            for (int a = 0; a < 4; a++) {
                u64 ap = pk2(av[a], av[a]);
#pragma unroll
                for (int q = 0; q < 4; q++) fma2(acc[a][q], ap, xj[q]);
            }
        }
    }
    __syncthreads();
#pragma unroll
    for (int a = 0; a < 4; a++)
#pragma unroll
        for (int q = 0; q < 4; q++) {
            float2 f = upk2(acc[a][q]);
            atomicAdd(&psum[kq * 4 + a][cg * 8 + 2 * q], f.x);
            atomicAdd(&psum[kq * 4 + a][cg * 8 + 2 * q + 1], f.y);
        }
    if (cg == 0)
#pragma unroll
        for (int a = 0; a < 4; a++) atomicAdd(&gps[kq * 4 + a], gpl[a]);
    __syncthreads();
    for (int i = tid; i < 2048; i += 256) {
        int kk = i >> 5, c = i & 31;
        atomicAdd(&g_pooled[((size_t)b * K2 + k0 + kk) * CIN + c], psum[kk][c]);
    }
    if (tid < 64) atomicAdd(&gp_out[b * K2 + k0 + tid], gps[tid]);
}

__global__ __launch_bounds__(256) void k_fc(const float* __restrict__ wf,
                                            const float* __restrict__ bf,
                                            int B, float invL) {
    int j = blockIdx.x, tid = threadIdx.x;
    const float* wrow = wf + (size_t)j * (K2 * CIN);
    float acc[MAXB];
#pragma unroll
    for (int b = 0; b < MAXB; b++) acc[b] = 0.f;
    for (int i = tid; i < K2 * CIN; i += 256) {
        float w = wrow[i];
#pragma unroll
        for (int b = 0; b < MAXB; b++)
            if (b < B) acc[b] += w * g_pooled[(size_t)b * (K2 * CIN) + i];
    }
    __shared__ float red[8][MAXB];
    int lane = tid & 31, w = tid >> 5;
#pragma unroll
    for (int b = 0; b < MAXB; b++) {
        float v = acc[b];
#pragma unroll
        for (int o = 16; o; o >>= 1) v += __shfl_down_sync(0xffffffffu, v, o);
        if (lane == 0) red[w][b] = v;
    }
    __syncthreads();
    if (tid < B) {
        float ssum = 0.f;
        for (int i = 0; i < 8; i++) ssum += red[i][tid];
        g_resraw[tid * FCD + j] = fmaf(ssum, invL, bf[j]);
    }
}

__global__ void k_final(float* __restrict__ outp, const float* __restrict__ gf,
                        const float* __restrict__ bef, int B, int L) {
    int j = threadIdx.x;
    __shared__ float rows[MAXB];
    if (j < B) rows[j] = 0.f;
    __syncthreads();
    float v[MAXB];
    float s = 0.f, q = 0.f;
    for (int b = 0; b < B; b++) {
        v[b] = g_resraw[b * FCD + j];
        s += v[b]; q += v[b] * v[b];
    }
    float invB = 1.f / (float)B;
    float mu = s * invB;
    float var = q * invB - mu * mu;
    float a = gf[j] * rsqrtf(var + 1e-5f);
    float c = fmaf(-mu, a, bef[j]);
    for (int b = 0; b < B; b++) {
        v[b] = fmaf(a, v[b], c);
        atomicAdd(&rows[b], v[b] * v[b]);
    }
    __syncthreads();
    for (int b = 0; b < B; b++)
        outp[b * FCD + j] = v[b] / fmaxf(sqrtf(rows[b]), 1e-12f);
    if (j < B) outp[B * FCD + B * K2 + j] = (float)L;
}

extern "C" void kernel_launch(void* const* d_in, const int* in_sizes, int n_in,
                              void* d_out, int out_size) {
    const float* x   = (const float*)d_in[0];
    const float* w1  = (const float*)d_in[1];
    const float* b1  = (const float*)d_in[2];
    const float* g1  = (const float*)d_in[3];
    const float* be1 = (const float*)d_in[4];
    const float* w2  = (const float*)d_in[5];
    const float* b2  = (const float*)d_in[6];
    const float* g2  = (const float*)d_in[7];
    const float* be2 = (const float*)d_in[8];
    const float* wf  = (const float*)d_in[9];
    const float* bf  = (const float*)d_in[10];
    const float* gf  = (const float*)d_in[11];
    const float* bef = (const float*)d_in[12];
    float* outp = (float*)d_out;

    int N = in_sizes[0] / CIN;
    int B = out_size / (FCD + K2 + 1);
    int L = N / B;
    float invN = 1.f / (float)N;
    float invL = 1.f / (float)L;

    cudaFuncSetAttribute(k_gemm2_mma, cudaFuncAttributeMaxDynamicSharedMemorySize, SM_TOTAL);

    k_zero<<<(B * K2 * CIN + 255) / 256, 256>>>(outp, B);
    k_prepb<<<(K2 * 16 + 255) / 256, 256>>>(w2);
    k_moments<<<N / 8192, 256>>>(x, N);
    k_fin1<<<1, K1>>>(w1, b1, g1, be1, invN);
    k_gemm1f<<<N / 256, 256>>>(x, w1, b1, N);
    k_gemm2_mma<<<dim3(4, N / 128), 256, SM_TOTAL>>>(b2, N);
    k_fin2<<<1, K2>>>(g2, be2, invN);
    k_pool<<<dim3(B, K2 / 64, 8), 256>>>(x, outp + B * FCD, L);
    k_fc<<<FCD, 256>>>(wf, bf, B, invL);
    k_final<<<1, FCD>>>(outp, gf, bef, B, L);
}